// round 1
// baseline (speedup 1.0000x reference)
#include <cuda_runtime.h>
#include <math.h>

// Problem constants
#define B_  2
#define S_  2048
#define E_  1024
#define H_  16
#define D_  64
#define NT  (B_*S_)      // 4096 tokens
#define F3  (3*E_)       // 3072 qkv features

// Scratch (device globals; no allocation allowed)
__device__ float g_q[(size_t)B_*H_*S_*D_];   // [BH, S, D]
__device__ float g_k[(size_t)B_*H_*S_*D_];
__device__ float g_v[(size_t)B_*H_*S_*D_];
__device__ float g_o[(size_t)NT*E_];         // [B, S, H, D] == [B,S,E]

// ---------------------------------------------------------------------------
// SGEMM NT: C[M,N] = A[M,K] * W[N,K]^T, 128x128x16 tile, 256 thr, 8x8/thread
// split-tile (4 + 4 with 64 offset) for conflict-free float4 shared reads.
// ---------------------------------------------------------------------------

// ---- Kernel 1: QKV projection with scatter epilogue into g_q/g_k/g_v ------
__global__ void __launch_bounds__(256) qkv_gemm_kernel(
    const float* __restrict__ X,     // [NT, E]
    const float* __restrict__ W)     // [3E, E]
{
    __shared__ float As[16][128];
    __shared__ float Bs[16][128];

    const int tid = threadIdx.x;
    const int tx = tid & 15;
    const int ty = tid >> 4;
    const int row0 = blockIdx.y * 128;   // token tile
    const int col0 = blockIdx.x * 128;   // feature tile

    float c[8][8];
    #pragma unroll
    for (int i = 0; i < 8; i++)
        #pragma unroll
        for (int j = 0; j < 8; j++) c[i][j] = 0.f;

    for (int k0 = 0; k0 < E_; k0 += 16) {
        // Load A and B tiles (transposed into [k][m])
        #pragma unroll
        for (int l = 0; l < 2; l++) {
            int idx = tid + l * 256;          // 0..511 float4 slots
            int r  = idx >> 2;                // 0..127
            int kc = (idx & 3) << 2;          // 0,4,8,12
            float4 va = *(const float4*)(X + (size_t)(row0 + r) * E_ + k0 + kc);
            As[kc + 0][r] = va.x; As[kc + 1][r] = va.y;
            As[kc + 2][r] = va.z; As[kc + 3][r] = va.w;
            float4 vb = *(const float4*)(W + (size_t)(col0 + r) * E_ + k0 + kc);
            Bs[kc + 0][r] = vb.x; Bs[kc + 1][r] = vb.y;
            Bs[kc + 2][r] = vb.z; Bs[kc + 3][r] = vb.w;
        }
        __syncthreads();

        #pragma unroll
        for (int k = 0; k < 16; k++) {
            float a[8], b[8];
            *(float4*)&a[0] = *(const float4*)&As[k][ty * 4];
            *(float4*)&a[4] = *(const float4*)&As[k][64 + ty * 4];
            *(float4*)&b[0] = *(const float4*)&Bs[k][tx * 4];
            *(float4*)&b[4] = *(const float4*)&Bs[k][64 + tx * 4];
            #pragma unroll
            for (int i = 0; i < 8; i++)
                #pragma unroll
                for (int j = 0; j < 8; j++)
                    c[i][j] = fmaf(a[i], b[j], c[i][j]);
        }
        __syncthreads();
    }

    // Scatter epilogue: f -> (which, h, d); t -> (b, s)
    #pragma unroll
    for (int i = 0; i < 8; i++) {
        int t = row0 + ((i < 4) ? (ty * 4 + i) : (64 + ty * 4 + i - 4));
        int bb = t >> 11;          // /S_
        int ss = t & (S_ - 1);
        #pragma unroll
        for (int j = 0; j < 8; j++) {
            int f = col0 + ((j < 4) ? (tx * 4 + j) : (64 + tx * 4 + j - 4));
            int which = f >> 10;
            int rem   = f & 1023;
            int h = rem >> 6;
            int d = rem & 63;
            float* dst = (which == 0) ? g_q : ((which == 1) ? g_k : g_v);
            dst[(((size_t)(bb * H_ + h)) * S_ + ss) * D_ + d] = c[i][j];
        }
    }
}

// ---- Kernel 3: output projection (plain NT GEMM, writes d_out) ------------
__global__ void __launch_bounds__(256) out_gemm_kernel(
    const float* __restrict__ A,     // g_o [NT, E]
    const float* __restrict__ W,     // w_out [E, E]
    float* __restrict__ C)           // d_out [NT, E]
{
    __shared__ float As[16][128];
    __shared__ float Bs[16][128];

    const int tid = threadIdx.x;
    const int tx = tid & 15;
    const int ty = tid >> 4;
    const int row0 = blockIdx.y * 128;
    const int col0 = blockIdx.x * 128;

    float c[8][8];
    #pragma unroll
    for (int i = 0; i < 8; i++)
        #pragma unroll
        for (int j = 0; j < 8; j++) c[i][j] = 0.f;

    for (int k0 = 0; k0 < E_; k0 += 16) {
        #pragma unroll
        for (int l = 0; l < 2; l++) {
            int idx = tid + l * 256;
            int r  = idx >> 2;
            int kc = (idx & 3) << 2;
            float4 va = *(const float4*)(A + (size_t)(row0 + r) * E_ + k0 + kc);
            As[kc + 0][r] = va.x; As[kc + 1][r] = va.y;
            As[kc + 2][r] = va.z; As[kc + 3][r] = va.w;
            float4 vb = *(const float4*)(W + (size_t)(col0 + r) * E_ + k0 + kc);
            Bs[kc + 0][r] = vb.x; Bs[kc + 1][r] = vb.y;
            Bs[kc + 2][r] = vb.z; Bs[kc + 3][r] = vb.w;
        }
        __syncthreads();

        #pragma unroll
        for (int k = 0; k < 16; k++) {
            float a[8], b[8];
            *(float4*)&a[0] = *(const float4*)&As[k][ty * 4];
            *(float4*)&a[4] = *(const float4*)&As[k][64 + ty * 4];
            *(float4*)&b[0] = *(const float4*)&Bs[k][tx * 4];
            *(float4*)&b[4] = *(const float4*)&Bs[k][64 + tx * 4];
            #pragma unroll
            for (int i = 0; i < 8; i++)
                #pragma unroll
                for (int j = 0; j < 8; j++)
                    c[i][j] = fmaf(a[i], b[j], c[i][j]);
        }
        __syncthreads();
    }

    #pragma unroll
    for (int i = 0; i < 8; i++) {
        int r = row0 + ((i < 4) ? (ty * 4 + i) : (64 + ty * 4 + i - 4));
        #pragma unroll
        for (int j = 0; j < 8; j++) {
            int f = col0 + ((j < 4) ? (tx * 4 + j) : (64 + tx * 4 + j - 4));
            C[(size_t)r * E_ + f] = c[i][j];
        }
    }
}

// ---------------------------------------------------------------------------
// Kernel 2: flash attention, causal, fp32. BM=BN=64, D=64.
// 256 threads: tx=tid&15 (cols), ty=tid>>4 (rows), 4x4 tile per thread.
// Dynamic smem: Qs[64][68] ([d][m]), KVs[64][68] (K:[d][n] then V:[n][d]),
//               Ps[64][68] ([n][m]). Stride 68 keeps 16B alignment, kills
//               bank conflicts.
// ---------------------------------------------------------------------------
#define LDP 68

__global__ void __launch_bounds__(256) attn_kernel(float* __restrict__ Og)
{
    extern __shared__ float sm[];
    float* Qs  = sm;                 // [d][m]
    float* KVs = sm + 64 * LDP;      // [d][n] for K, [n][d] for V
    float* Ps  = sm + 2 * 64 * LDP;  // [n][m]

    const int qb = blockIdx.x;       // 0..31 (query block)
    const int bh = blockIdx.y;       // 0..31 (batch*head)
    const int bb = bh / H_;
    const int hh = bh % H_;

    const float* Qg = g_q + ((size_t)bh * S_ + qb * 64) * D_;
    const float* Kg = g_k + (size_t)bh * S_ * D_;
    const float* Vg = g_v + (size_t)bh * S_ * D_;

    const int tid = threadIdx.x;
    const int tx = tid & 15;
    const int ty = tid >> 4;

    const float scale = 0.125f;      // 1/sqrt(64)

    // Load Q tile transposed with scale folded in: Qs[d][m] = Q[m][d]*scale
    #pragma unroll
    for (int l = 0; l < 4; l++) {
        int idx = l * 256 + tid;     // 0..1023 float4 slots
        int r  = idx >> 4;           // m: 0..63
        int c4 = (idx & 15) << 2;    // d: 0,4,...,60
        float4 v = *(const float4*)(Qg + (size_t)r * D_ + c4);
        Qs[(c4 + 0) * LDP + r] = v.x * scale;
        Qs[(c4 + 1) * LDP + r] = v.y * scale;
        Qs[(c4 + 2) * LDP + r] = v.z * scale;
        Qs[(c4 + 3) * LDP + r] = v.w * scale;
    }

    float o[4][4];
    float mrow[4], lrow[4];
    #pragma unroll
    for (int i = 0; i < 4; i++) {
        mrow[i] = -1e30f; lrow[i] = 0.f;
        #pragma unroll
        for (int j = 0; j < 4; j++) o[i][j] = 0.f;
    }

    for (int kb = 0; kb <= qb; kb++) {
        __syncthreads();   // prev PV reads done; also orders Q load on iter 0

        // Load K tile transposed: KVs[d][n] = K[kb*64+n][d]
        #pragma unroll
        for (int l = 0; l < 4; l++) {
            int idx = l * 256 + tid;
            int r  = idx >> 4;            // n
            int c4 = (idx & 15) << 2;     // d
            float4 v = *(const float4*)(Kg + (size_t)(kb * 64 + r) * D_ + c4);
            KVs[(c4 + 0) * LDP + r] = v.x;
            KVs[(c4 + 1) * LDP + r] = v.y;
            KVs[(c4 + 2) * LDP + r] = v.z;
            KVs[(c4 + 3) * LDP + r] = v.w;
        }
        __syncthreads();

        // Scores S = (Q*scale) . K^T : s[i][j], rows ty*4+i, cols tx*4+j
        float s[4][4];
        #pragma unroll
        for (int i = 0; i < 4; i++)
            #pragma unroll
            for (int j = 0; j < 4; j++) s[i][j] = 0.f;

        #pragma unroll 8
        for (int d = 0; d < 64; d++) {
            float a[4], b[4];
            *(float4*)a = *(const float4*)&Qs[d * LDP + ty * 4];
            *(float4*)b = *(const float4*)&KVs[d * LDP + tx * 4];
            #pragma unroll
            for (int i = 0; i < 4; i++)
                #pragma unroll
                for (int j = 0; j < 4; j++)
                    s[i][j] = fmaf(a[i], b[j], s[i][j]);
        }

        // Causal mask (only diagonal block needs it)
        if (kb == qb) {
            #pragma unroll
            for (int i = 0; i < 4; i++) {
                int im = qb * 64 + ty * 4 + i;
                #pragma unroll
                for (int j = 0; j < 4; j++) {
                    int jn = kb * 64 + tx * 4 + j;
                    if (jn > im) s[i][j] = -1e30f;
                }
            }
        }

        // Online softmax per row (16 threads share a row-group via shfl)
        #pragma unroll
        for (int i = 0; i < 4; i++) {
            float rmax = s[i][0];
            #pragma unroll
            for (int j = 1; j < 4; j++) rmax = fmaxf(rmax, s[i][j]);
            #pragma unroll
            for (int w = 1; w < 16; w <<= 1)
                rmax = fmaxf(rmax, __shfl_xor_sync(0xffffffffu, rmax, w));

            float mnew = fmaxf(mrow[i], rmax);
            float corr = __expf(mrow[i] - mnew);
            mrow[i] = mnew;
            lrow[i] *= corr;
            #pragma unroll
            for (int j = 0; j < 4; j++) o[i][j] *= corr;

            float rsum = 0.f;
            #pragma unroll
            for (int j = 0; j < 4; j++) {
                float p = __expf(s[i][j] - mnew);
                s[i][j] = p;
                rsum += p;
            }
            #pragma unroll
            for (int w = 1; w < 16; w <<= 1)
                rsum += __shfl_xor_sync(0xffffffffu, rsum, w);
            lrow[i] += rsum;
        }

        // Write P transposed: Ps[n][m]
        #pragma unroll
        for (int i = 0; i < 4; i++)
            #pragma unroll
            for (int j = 0; j < 4; j++)
                Ps[(tx * 4 + j) * LDP + ty * 4 + i] = s[i][j];

        __syncthreads();  // P visible; K reads finished

        // Load V tile (no transpose): KVs[n][d] = V[kb*64+n][d]
        #pragma unroll
        for (int l = 0; l < 4; l++) {
            int idx = l * 256 + tid;
            int r  = idx >> 4;            // n
            int c4 = (idx & 15) << 2;     // d
            float4 v = *(const float4*)(Vg + (size_t)(kb * 64 + r) * D_ + c4);
            *(float4*)&KVs[r * LDP + c4] = v;
        }
        __syncthreads();

        // O += P . V
        #pragma unroll 8
        for (int n = 0; n < 64; n++) {
            float a[4], b[4];
            *(float4*)a = *(const float4*)&Ps[n * LDP + ty * 4];
            *(float4*)b = *(const float4*)&KVs[n * LDP + tx * 4];
            #pragma unroll
            for (int i = 0; i < 4; i++)
                #pragma unroll
                for (int j = 0; j < 4; j++)
                    o[i][j] = fmaf(a[i], b[j], o[i][j]);
        }
    }

    // Store: Og[b][s][h][d], s = qb*64 + ty*4+i, d = tx*4+j
    #pragma unroll
    for (int i = 0; i < 4; i++) {
        int srow = qb * 64 + ty * 4 + i;
        float inv = 1.0f / lrow[i];
        #pragma unroll
        for (int j = 0; j < 4; j++) {
            Og[((size_t)(bb * S_ + srow)) * E_ + hh * D_ + tx * 4 + j] = o[i][j] * inv;
        }
    }
}

// ---------------------------------------------------------------------------
extern "C" void kernel_launch(void* const* d_in, const int* in_sizes, int n_in,
                              void* d_out, int out_size)
{
    const float* x     = (const float*)d_in[0];   // [B,S,E]
    const float* w_qkv = (const float*)d_in[1];   // [3E,E]
    const float* w_out = (const float*)d_in[2];   // [E,E]
    float* out = (float*)d_out;                   // [B,S,E]

    float* q; cudaGetSymbolAddress((void**)&q, g_q);
    float* og; cudaGetSymbolAddress((void**)&og, g_o);
    (void)q; (void)og;

    // 1) QKV projection
    {
        dim3 grid(F3 / 128, NT / 128);   // (24, 32)
        qkv_gemm_kernel<<<grid, 256>>>(x, w_qkv);
    }

    // 2) Flash attention (causal)
    {
        static bool attr_set = false;
        if (!attr_set) {
            cudaFuncSetAttribute(attn_kernel,
                                 cudaFuncAttributeMaxDynamicSharedMemorySize,
                                 3 * 64 * LDP * 4);
            attr_set = true;
        }
        dim3 grid(S_ / 64, B_ * H_);     // (32, 32)
        attn_kernel<<<grid, 256, 3 * 64 * LDP * 4>>>(og);
    }

    // 3) Output projection
    {
        dim3 grid(E_ / 128, NT / 128);   // (8, 32)
        out_gemm_kernel<<<grid, 256>>>(og, w_out, out);
    }
}

// round 3
// speedup vs baseline: 1.3724x; 1.3724x over previous
#include <cuda_runtime.h>
#include <cuda_bf16.h>
#include <cstdint>
#include <math.h>

// Problem constants
#define B_  2
#define S_  2048
#define E_  1024
#define H_  16
#define D_  64
#define NT  (B_*S_)      // 4096 tokens
#define F3  (3*E_)       // 3072 qkv features

// ---------------------------------------------------------------------------
// Device-global scratch (no allocation allowed)
// ---------------------------------------------------------------------------
__device__ float g_q[(size_t)B_*H_*S_*D_];   // [BH, S, D]
__device__ float g_k[(size_t)B_*H_*S_*D_];
__device__ float g_v[(size_t)B_*H_*S_*D_];
__device__ float g_o[(size_t)NT*E_];         // [B, S, H, D] == [B,S,E]

__device__ __nv_bfloat16 g_xhi[(size_t)NT*E_],  g_xlo[(size_t)NT*E_];
__device__ __nv_bfloat16 g_wqhi[(size_t)F3*E_], g_wqlo[(size_t)F3*E_];
__device__ __nv_bfloat16 g_wohi[(size_t)E_*E_], g_wolo[(size_t)E_*E_];
__device__ __nv_bfloat16 g_ohi[(size_t)NT*E_],  g_olo[(size_t)NT*E_];

// ---------------------------------------------------------------------------
// Warp-level tensor-core helpers (portable PTX: sm_80+, assembles on sm_103)
// ---------------------------------------------------------------------------
__device__ __forceinline__ uint32_t smem_to_u32(const void* p) {
    uint32_t a;
    asm("{ .reg .u64 t; cvta.to.shared.u64 t, %1; cvt.u32.u64 %0, t; }"
        : "=r"(a) : "l"(p));
    return a;
}

__device__ __forceinline__ void ldsm_x4(uint32_t& r0, uint32_t& r1,
                                        uint32_t& r2, uint32_t& r3,
                                        uint32_t addr) {
    asm volatile("ldmatrix.sync.aligned.m8n8.x4.shared.b16 {%0,%1,%2,%3}, [%4];"
        : "=r"(r0), "=r"(r1), "=r"(r2), "=r"(r3) : "r"(addr));
}

__device__ __forceinline__ void mma_bf16(float c[4],
                                         uint32_t a0, uint32_t a1,
                                         uint32_t a2, uint32_t a3,
                                         uint32_t b0, uint32_t b1) {
    asm volatile(
        "mma.sync.aligned.m16n8k16.row.col.f32.bf16.bf16.f32 "
        "{%0,%1,%2,%3}, {%4,%5,%6,%7}, {%8,%9}, {%0,%1,%2,%3};"
        : "+f"(c[0]), "+f"(c[1]), "+f"(c[2]), "+f"(c[3])
        : "r"(a0), "r"(a1), "r"(a2), "r"(a3), "r"(b0), "r"(b1));
}

// ---------------------------------------------------------------------------
// fp32 -> bf16 hi/lo split
// ---------------------------------------------------------------------------
__global__ void __launch_bounds__(256) split_kernel(
    const float* __restrict__ in,
    __nv_bfloat16* __restrict__ hi, __nv_bfloat16* __restrict__ lo, int n4)
{
    int i = blockIdx.x * blockDim.x + threadIdx.x;
    if (i >= n4) return;
    float4 v = ((const float4*)in)[i];
    float f[4] = {v.x, v.y, v.z, v.w};
    unsigned short hs[4], ls[4];
    #pragma unroll
    for (int j = 0; j < 4; j++) {
        __nv_bfloat16 h = __float2bfloat16(f[j]);
        __nv_bfloat16 l = __float2bfloat16(f[j] - __bfloat162float(h));
        hs[j] = *(unsigned short*)&h;
        ls[j] = *(unsigned short*)&l;
    }
    ((ushort4*)hi)[i] = make_ushort4(hs[0], hs[1], hs[2], hs[3]);
    ((ushort4*)lo)[i] = make_ushort4(ls[0], ls[1], ls[2], ls[3]);
}

// ---------------------------------------------------------------------------
// bf16-split mma.sync GEMM: C[M,N] = A[M,K] * B[N,K]^T (fp32-equivalent).
// CTA tile 128x128, K-chunk 32, 8 warps (4m x 2n), warp tile 32x64.
// Double-buffered SMEM, global->reg prefetch overlap.
// mode 0: scatter into g_q/g_k/g_v; mode 1: plain store to Cplain.
// ---------------------------------------------------------------------------
#define KC    32
#define LDA   40                      // bf16 per smem row (32 + 8 pad)
#define TILEB (128*LDA*2)             // 10240 bytes per tile
#define BUFB  (4*TILEB)               // 40960 bytes (Ahi,Alo,Bhi,Blo)
#define GEMM_SMEM (2*BUFB)            // 81920

__global__ void __launch_bounds__(256) mma_gemm_kernel(
    const __nv_bfloat16* __restrict__ Ahi, const __nv_bfloat16* __restrict__ Alo,
    const __nv_bfloat16* __restrict__ Bhi, const __nv_bfloat16* __restrict__ Blo,
    float* __restrict__ Cplain, int mode)
{
    extern __shared__ char smc[];
    const uint32_t sb = smem_to_u32(smc);
    const int tid  = threadIdx.x;
    const int wid  = tid >> 5;
    const int lane = tid & 31;
    const int warp_m = (wid & 3) * 32;
    const int warp_n = (wid >> 2) * 64;
    const int row0 = blockIdx.y * 128;
    const int col0 = blockIdx.x * 128;

    float C[2][8][4];
    #pragma unroll
    for (int mi = 0; mi < 2; mi++)
        #pragma unroll
        for (int nf = 0; nf < 8; nf++)
            #pragma unroll
            for (int e = 0; e < 4; e++) C[mi][nf][e] = 0.f;

    // per-thread load coords: idx = l*256+tid -> r=idx>>2 (row), cc=idx&3
    const int r_ld[2]  = { tid >> 2, (256 + tid) >> 2 };
    const int cc_ld    = tid & 3;                    // same for both l
    const uint32_t so_ld[2] = {
        (uint32_t)(r_ld[0] * 80 + cc_ld * 16),
        (uint32_t)(r_ld[1] * 80 + cc_ld * 16)
    };

    float4 pa_hi[2], pa_lo[2], pb_hi[2], pb_lo[2];

    // ---- prologue: load chunk 0 into buffer 0 ----
    #pragma unroll
    for (int l = 0; l < 2; l++) {
        size_t ga = (size_t)(row0 + r_ld[l]) * E_ + cc_ld * 8;
        size_t gb = (size_t)(col0 + r_ld[l]) * E_ + cc_ld * 8;
        pa_hi[l] = *(const float4*)(Ahi + ga);
        pa_lo[l] = *(const float4*)(Alo + ga);
        pb_hi[l] = *(const float4*)(Bhi + gb);
        pb_lo[l] = *(const float4*)(Blo + gb);
    }
    #pragma unroll
    for (int l = 0; l < 2; l++) {
        *(float4*)(smc + 0*TILEB + so_ld[l]) = pa_hi[l];
        *(float4*)(smc + 1*TILEB + so_ld[l]) = pa_lo[l];
        *(float4*)(smc + 2*TILEB + so_ld[l]) = pb_hi[l];
        *(float4*)(smc + 3*TILEB + so_ld[l]) = pb_lo[l];
    }
    __syncthreads();

    const int NCH = E_ / KC;   // 32

    #pragma unroll 1
    for (int c = 0; c < NCH; c++) {
        const int p = c & 1;

        // prefetch chunk c+1 (global -> regs)
        if (c + 1 < NCH) {
            const int k0 = (c + 1) * KC;
            #pragma unroll
            for (int l = 0; l < 2; l++) {
                size_t ga = (size_t)(row0 + r_ld[l]) * E_ + k0 + cc_ld * 8;
                size_t gb = (size_t)(col0 + r_ld[l]) * E_ + k0 + cc_ld * 8;
                pa_hi[l] = *(const float4*)(Ahi + ga);
                pa_lo[l] = *(const float4*)(Alo + ga);
                pb_hi[l] = *(const float4*)(Bhi + gb);
                pb_lo[l] = *(const float4*)(Blo + gb);
            }
        }

        // ---- compute from buffer p ----
        const uint32_t bAhi = sb + p * BUFB + 0 * TILEB;
        const uint32_t bAlo = sb + p * BUFB + 1 * TILEB;
        const uint32_t bBhi = sb + p * BUFB + 2 * TILEB;
        const uint32_t bBlo = sb + p * BUFB + 3 * TILEB;

        #pragma unroll
        for (int ki = 0; ki < 2; ki++) {
            const int kf = ki * 16;
            // A fragments (both planes, both m halves)
            uint32_t ah[2][4], al[2][4];
            {
                const uint32_t acol = (uint32_t)((kf + ((lane >> 4) << 3)) * 2);
                #pragma unroll
                for (int mi = 0; mi < 2; mi++) {
                    uint32_t ao = (uint32_t)((warp_m + mi * 16 + (lane & 15)) * 80) + acol;
                    ldsm_x4(ah[mi][0], ah[mi][1], ah[mi][2], ah[mi][3], bAhi + ao);
                    ldsm_x4(al[mi][0], al[mi][1], al[mi][2], al[mi][3], bAlo + ao);
                }
            }
            // B fragments in n-pairs: x4 = tiles (nj,k0)(nj,k8)(nj+1,k0)(nj+1,k8)
            const uint32_t brow_off = (uint32_t)((lane & 7) + ((lane >> 4) & 1) * 8);
            const uint32_t bcol     = (uint32_t)((kf + ((lane >> 3) & 1) * 8) * 2);
            #pragma unroll
            for (int nj = 0; nj < 4; nj++) {
                uint32_t bo = (uint32_t)((warp_n + nj * 16 + brow_off) * 80) + bcol;
                uint32_t bh0, bh1, bh2, bh3, bl0, bl1, bl2, bl3;
                ldsm_x4(bh0, bh1, bh2, bh3, bBhi + bo);
                ldsm_x4(bl0, bl1, bl2, bl3, bBlo + bo);
                #pragma unroll
                for (int mi = 0; mi < 2; mi++) {
                    float* c0 = C[mi][nj * 2];
                    float* c1 = C[mi][nj * 2 + 1];
                    mma_bf16(c0, ah[mi][0], ah[mi][1], ah[mi][2], ah[mi][3], bh0, bh1);
                    mma_bf16(c0, al[mi][0], al[mi][1], al[mi][2], al[mi][3], bh0, bh1);
                    mma_bf16(c0, ah[mi][0], ah[mi][1], ah[mi][2], ah[mi][3], bl0, bl1);
                    mma_bf16(c1, ah[mi][0], ah[mi][1], ah[mi][2], ah[mi][3], bh2, bh3);
                    mma_bf16(c1, al[mi][0], al[mi][1], al[mi][2], al[mi][3], bh2, bh3);
                    mma_bf16(c1, ah[mi][0], ah[mi][1], ah[mi][2], ah[mi][3], bl2, bl3);
                }
            }
        }

        // ---- store prefetched chunk into the other buffer ----
        if (c + 1 < NCH) {
            __syncthreads();   // everyone done reading buffer p^1 (chunk c-1)
            const int q = (c + 1) & 1;
            #pragma unroll
            for (int l = 0; l < 2; l++) {
                *(float4*)(smc + q * BUFB + 0 * TILEB + so_ld[l]) = pa_hi[l];
                *(float4*)(smc + q * BUFB + 1 * TILEB + so_ld[l]) = pa_lo[l];
                *(float4*)(smc + q * BUFB + 2 * TILEB + so_ld[l]) = pb_hi[l];
                *(float4*)(smc + q * BUFB + 3 * TILEB + so_ld[l]) = pb_lo[l];
            }
            __syncthreads();
        }
    }

    // ---- epilogue ----
    if (mode == 0) {
        #pragma unroll
        for (int mi = 0; mi < 2; mi++) {
            #pragma unroll
            for (int half = 0; half < 2; half++) {
                int t = row0 + warp_m + mi * 16 + (lane >> 2) + half * 8;
                int bb = t >> 11;
                int ss = t & (S_ - 1);
                #pragma unroll
                for (int nf = 0; nf < 8; nf++) {
                    int f = col0 + warp_n + nf * 8 + (lane & 3) * 2;
                    int which = f >> 10;
                    int rem = f & 1023;
                    int h = rem >> 6;
                    int d = rem & 63;
                    float* dst = (which == 0) ? g_q : ((which == 1) ? g_k : g_v);
                    float2 v = make_float2(C[mi][nf][half * 2],
                                           C[mi][nf][half * 2 + 1]);
                    *(float2*)(dst + (((size_t)(bb * H_ + h)) * S_ + ss) * D_ + d) = v;
                }
            }
        }
    } else {
        #pragma unroll
        for (int mi = 0; mi < 2; mi++) {
            #pragma unroll
            for (int half = 0; half < 2; half++) {
                int r = row0 + warp_m + mi * 16 + (lane >> 2) + half * 8;
                #pragma unroll
                for (int nf = 0; nf < 8; nf++) {
                    int f = col0 + warp_n + nf * 8 + (lane & 3) * 2;
                    float2 v = make_float2(C[mi][nf][half * 2],
                                           C[mi][nf][half * 2 + 1]);
                    *(float2*)(Cplain + (size_t)r * E_ + f) = v;
                }
            }
        }
    }
}

// ---------------------------------------------------------------------------
// Flash attention, causal, fp32 (unchanged). BM=BN=64, D=64.
// ---------------------------------------------------------------------------
#define LDP 68

__global__ void __launch_bounds__(256) attn_kernel(float* __restrict__ Og)
{
    extern __shared__ float sm[];
    float* Qs  = sm;
    float* KVs = sm + 64 * LDP;
    float* Ps  = sm + 2 * 64 * LDP;

    const int qb = blockIdx.x;
    const int bh = blockIdx.y;
    const int bb = bh / H_;
    const int hh = bh % H_;

    const float* Qg = g_q + ((size_t)bh * S_ + qb * 64) * D_;
    const float* Kg = g_k + (size_t)bh * S_ * D_;
    const float* Vg = g_v + (size_t)bh * S_ * D_;

    const int tid = threadIdx.x;
    const int tx = tid & 15;
    const int ty = tid >> 4;

    const float scale = 0.125f;

    #pragma unroll
    for (int l = 0; l < 4; l++) {
        int idx = l * 256 + tid;
        int r  = idx >> 4;
        int c4 = (idx & 15) << 2;
        float4 v = *(const float4*)(Qg + (size_t)r * D_ + c4);
        Qs[(c4 + 0) * LDP + r] = v.x * scale;
        Qs[(c4 + 1) * LDP + r] = v.y * scale;
        Qs[(c4 + 2) * LDP + r] = v.z * scale;
        Qs[(c4 + 3) * LDP + r] = v.w * scale;
    }

    float o[4][4];
    float mrow[4], lrow[4];
    #pragma unroll
    for (int i = 0; i < 4; i++) {
        mrow[i] = -1e30f; lrow[i] = 0.f;
        #pragma unroll
        for (int j = 0; j < 4; j++) o[i][j] = 0.f;
    }

    for (int kb = 0; kb <= qb; kb++) {
        __syncthreads();

        #pragma unroll
        for (int l = 0; l < 4; l++) {
            int idx = l * 256 + tid;
            int r  = idx >> 4;
            int c4 = (idx & 15) << 2;
            float4 v = *(const float4*)(Kg + (size_t)(kb * 64 + r) * D_ + c4);
            KVs[(c4 + 0) * LDP + r] = v.x;
            KVs[(c4 + 1) * LDP + r] = v.y;
            KVs[(c4 + 2) * LDP + r] = v.z;
            KVs[(c4 + 3) * LDP + r] = v.w;
        }
        __syncthreads();

        float s[4][4];
        #pragma unroll
        for (int i = 0; i < 4; i++)
            #pragma unroll
            for (int j = 0; j < 4; j++) s[i][j] = 0.f;

        #pragma unroll 8
        for (int d = 0; d < 64; d++) {
            float a[4], b[4];
            *(float4*)a = *(const float4*)&Qs[d * LDP + ty * 4];
            *(float4*)b = *(const float4*)&KVs[d * LDP + tx * 4];
            #pragma unroll
            for (int i = 0; i < 4; i++)
                #pragma unroll
                for (int j = 0; j < 4; j++)
                    s[i][j] = fmaf(a[i], b[j], s[i][j]);
        }

        if (kb == qb) {
            #pragma unroll
            for (int i = 0; i < 4; i++) {
                int im = qb * 64 + ty * 4 + i;
                #pragma unroll
                for (int j = 0; j < 4; j++) {
                    int jn = kb * 64 + tx * 4 + j;
                    if (jn > im) s[i][j] = -1e30f;
                }
            }
        }

        #pragma unroll
        for (int i = 0; i < 4; i++) {
            float rmax = s[i][0];
            #pragma unroll
            for (int j = 1; j < 4; j++) rmax = fmaxf(rmax, s[i][j]);
            #pragma unroll
            for (int w = 1; w < 16; w <<= 1)
                rmax = fmaxf(rmax, __shfl_xor_sync(0xffffffffu, rmax, w));

            float mnew = fmaxf(mrow[i], rmax);
            float corr = __expf(mrow[i] - mnew);
            mrow[i] = mnew;
            lrow[i] *= corr;
            #pragma unroll
            for (int j = 0; j < 4; j++) o[i][j] *= corr;

            float rsum = 0.f;
            #pragma unroll
            for (int j = 0; j < 4; j++) {
                float p = __expf(s[i][j] - mnew);
                s[i][j] = p;
                rsum += p;
            }
            #pragma unroll
            for (int w = 1; w < 16; w <<= 1)
                rsum += __shfl_xor_sync(0xffffffffu, rsum, w);
            lrow[i] += rsum;
        }

        #pragma unroll
        for (int i = 0; i < 4; i++)
            #pragma unroll
            for (int j = 0; j < 4; j++)
                Ps[(tx * 4 + j) * LDP + ty * 4 + i] = s[i][j];

        __syncthreads();

        #pragma unroll
        for (int l = 0; l < 4; l++) {
            int idx = l * 256 + tid;
            int r  = idx >> 4;
            int c4 = (idx & 15) << 2;
            float4 v = *(const float4*)(Vg + (size_t)(kb * 64 + r) * D_ + c4);
            *(float4*)&KVs[r * LDP + c4] = v;
        }
        __syncthreads();

        #pragma unroll 8
        for (int n = 0; n < 64; n++) {
            float a[4], b[4];
            *(float4*)a = *(const float4*)&Ps[n * LDP + ty * 4];
            *(float4*)b = *(const float4*)&KVs[n * LDP + tx * 4];
            #pragma unroll
            for (int i = 0; i < 4; i++)
                #pragma unroll
                for (int j = 0; j < 4; j++)
                    o[i][j] = fmaf(a[i], b[j], o[i][j]);
        }
    }

    #pragma unroll
    for (int i = 0; i < 4; i++) {
        int srow = qb * 64 + ty * 4 + i;
        float inv = 1.0f / lrow[i];
        #pragma unroll
        for (int j = 0; j < 4; j++) {
            Og[((size_t)(bb * S_ + srow)) * E_ + hh * D_ + tx * 4 + j] = o[i][j] * inv;
        }
    }
}

// ---------------------------------------------------------------------------
extern "C" void kernel_launch(void* const* d_in, const int* in_sizes, int n_in,
                              void* d_out, int out_size)
{
    const float* x     = (const float*)d_in[0];   // [B,S,E]
    const float* w_qkv = (const float*)d_in[1];   // [3E,E]
    const float* w_out = (const float*)d_in[2];   // [E,E]
    float* out = (float*)d_out;                   // [B,S,E]

    float* og;  cudaGetSymbolAddress((void**)&og,  g_o);
    __nv_bfloat16 *xhi, *xlo, *wqhi, *wqlo, *wohi, *wolo, *ohi, *olo;
    cudaGetSymbolAddress((void**)&xhi,  g_xhi);
    cudaGetSymbolAddress((void**)&xlo,  g_xlo);
    cudaGetSymbolAddress((void**)&wqhi, g_wqhi);
    cudaGetSymbolAddress((void**)&wqlo, g_wqlo);
    cudaGetSymbolAddress((void**)&wohi, g_wohi);
    cudaGetSymbolAddress((void**)&wolo, g_wolo);
    cudaGetSymbolAddress((void**)&ohi,  g_ohi);
    cudaGetSymbolAddress((void**)&olo,  g_olo);

    static bool attr_set = false;
    if (!attr_set) {
        cudaFuncSetAttribute(mma_gemm_kernel,
                             cudaFuncAttributeMaxDynamicSharedMemorySize,
                             GEMM_SMEM);
        cudaFuncSetAttribute(attn_kernel,
                             cudaFuncAttributeMaxDynamicSharedMemorySize,
                             3 * 64 * LDP * 4);
        attr_set = true;
    }

    // 0) fp32 -> bf16 hi/lo splits for X and weights
    {
        int n4 = NT * E_ / 4;
        split_kernel<<<n4 / 256, 256>>>(x, xhi, xlo, n4);
        n4 = F3 * E_ / 4;
        split_kernel<<<n4 / 256, 256>>>(w_qkv, wqhi, wqlo, n4);
        n4 = E_ * E_ / 4;
        split_kernel<<<n4 / 256, 256>>>(w_out, wohi, wolo, n4);
    }

    // 1) QKV projection (tensor cores), scatter into g_q/g_k/g_v
    {
        dim3 grid(F3 / 128, NT / 128);   // (24, 32)
        mma_gemm_kernel<<<grid, 256, GEMM_SMEM>>>(
            xhi, xlo, wqhi, wqlo, nullptr, 0);
    }

    // 2) Flash attention (causal, fp32)
    {
        dim3 grid(S_ / 64, B_ * H_);     // (32, 32)
        attn_kernel<<<grid, 256, 3 * 64 * LDP * 4>>>(og);
    }

    // 3) Split attention output, then output projection (tensor cores)
    {
        int n4 = NT * E_ / 4;
        split_kernel<<<n4 / 256, 256>>>(og, ohi, olo, n4);
        dim3 grid(E_ / 128, NT / 128);   // (8, 32)
        mma_gemm_kernel<<<grid, 256, GEMM_SMEM>>>(
            ohi, olo, wohi, wolo, out, 1);
    }
}

// round 4
// speedup vs baseline: 2.4886x; 1.8133x over previous
#include <cuda_runtime.h>
#include <cuda_bf16.h>
#include <cstdint>
#include <math.h>

// Problem constants
#define B_  2
#define S_  2048
#define E_  1024
#define H_  16
#define D_  64
#define NT  (B_*S_)      // 4096 tokens
#define F3  (3*E_)       // 3072 qkv features

// ---------------------------------------------------------------------------
// Device-global scratch (no allocation allowed)
// ---------------------------------------------------------------------------
#define QKV_ELEMS ((size_t)B_*H_*S_*D_)
__device__ __nv_bfloat16 g_qhi[QKV_ELEMS], g_qlo[QKV_ELEMS];
__device__ __nv_bfloat16 g_khi[QKV_ELEMS], g_klo[QKV_ELEMS];
__device__ __nv_bfloat16 g_vhi[QKV_ELEMS], g_vlo[QKV_ELEMS];

__device__ __nv_bfloat16 g_xhi[(size_t)NT*E_],  g_xlo[(size_t)NT*E_];
__device__ __nv_bfloat16 g_wqhi[(size_t)F3*E_], g_wqlo[(size_t)F3*E_];
__device__ __nv_bfloat16 g_wohi[(size_t)E_*E_], g_wolo[(size_t)E_*E_];
__device__ __nv_bfloat16 g_ohi[(size_t)NT*E_],  g_olo[(size_t)NT*E_];

// ---------------------------------------------------------------------------
// Warp-level tensor-core helpers (portable PTX: sm_80+, assembles on sm_103)
// ---------------------------------------------------------------------------
__device__ __forceinline__ uint32_t smem_to_u32(const void* p) {
    uint32_t a;
    asm("{ .reg .u64 t; cvta.to.shared.u64 t, %1; cvt.u32.u64 %0, t; }"
        : "=r"(a) : "l"(p));
    return a;
}

__device__ __forceinline__ void ldsm_x4(uint32_t& r0, uint32_t& r1,
                                        uint32_t& r2, uint32_t& r3,
                                        uint32_t addr) {
    asm volatile("ldmatrix.sync.aligned.m8n8.x4.shared.b16 {%0,%1,%2,%3}, [%4];"
        : "=r"(r0), "=r"(r1), "=r"(r2), "=r"(r3) : "r"(addr));
}
__device__ __forceinline__ void ldsm_x4_trans(uint32_t& r0, uint32_t& r1,
                                              uint32_t& r2, uint32_t& r3,
                                              uint32_t addr) {
    asm volatile("ldmatrix.sync.aligned.m8n8.x4.trans.shared.b16 {%0,%1,%2,%3}, [%4];"
        : "=r"(r0), "=r"(r1), "=r"(r2), "=r"(r3) : "r"(addr));
}

__device__ __forceinline__ void mma_bf16(float c[4],
                                         uint32_t a0, uint32_t a1,
                                         uint32_t a2, uint32_t a3,
                                         uint32_t b0, uint32_t b1) {
    asm volatile(
        "mma.sync.aligned.m16n8k16.row.col.f32.bf16.bf16.f32 "
        "{%0,%1,%2,%3}, {%4,%5,%6,%7}, {%8,%9}, {%0,%1,%2,%3};"
        : "+f"(c[0]), "+f"(c[1]), "+f"(c[2]), "+f"(c[3])
        : "r"(a0), "r"(a1), "r"(a2), "r"(a3), "r"(b0), "r"(b1));
}

// pack two fp32 into bf16x2 (lo half = p0) and residual bf16x2
__device__ __forceinline__ void split_pack(float p0, float p1,
                                           uint32_t& hi2, uint32_t& lo2) {
    __nv_bfloat162 h = __floats2bfloat162_rn(p0, p1);
    float r0 = p0 - __bfloat162float(h.x);
    float r1 = p1 - __bfloat162float(h.y);
    __nv_bfloat162 l = __floats2bfloat162_rn(r0, r1);
    hi2 = *(uint32_t*)&h;
    lo2 = *(uint32_t*)&l;
}

// ---------------------------------------------------------------------------
// fp32 -> bf16 hi/lo split
// ---------------------------------------------------------------------------
__global__ void __launch_bounds__(256) split_kernel(
    const float* __restrict__ in,
    __nv_bfloat16* __restrict__ hi, __nv_bfloat16* __restrict__ lo, int n4)
{
    int i = blockIdx.x * blockDim.x + threadIdx.x;
    if (i >= n4) return;
    float4 v = ((const float4*)in)[i];
    float f[4] = {v.x, v.y, v.z, v.w};
    unsigned short hs[4], ls[4];
    #pragma unroll
    for (int j = 0; j < 4; j++) {
        __nv_bfloat16 h = __float2bfloat16(f[j]);
        __nv_bfloat16 l = __float2bfloat16(f[j] - __bfloat162float(h));
        hs[j] = *(unsigned short*)&h;
        ls[j] = *(unsigned short*)&l;
    }
    ((ushort4*)hi)[i] = make_ushort4(hs[0], hs[1], hs[2], hs[3]);
    ((ushort4*)lo)[i] = make_ushort4(ls[0], ls[1], ls[2], ls[3]);
}

// ---------------------------------------------------------------------------
// bf16-split mma.sync GEMM: C[M,N] = A[M,K] * B[N,K]^T (fp32-equivalent).
// CTA tile 128x128, K-chunk 32, 8 warps (4m x 2n), warp tile 32x64.
// mode 0: QKV — split results into g_{q,k,v}{hi,lo} planes (Q scaled 0.125)
// mode 1: plain fp32 store to Cplain.
// ---------------------------------------------------------------------------
#define KC    32
#define LDA   40
#define TILEB (128*LDA*2)             // 10240 bytes per tile
#define BUFB  (4*TILEB)               // 40960 bytes (Ahi,Alo,Bhi,Blo)
#define GEMM_SMEM (2*BUFB)            // 81920

__global__ void __launch_bounds__(256) mma_gemm_kernel(
    const __nv_bfloat16* __restrict__ Ahi, const __nv_bfloat16* __restrict__ Alo,
    const __nv_bfloat16* __restrict__ Bhi, const __nv_bfloat16* __restrict__ Blo,
    float* __restrict__ Cplain, int mode)
{
    extern __shared__ char smc[];
    const uint32_t sb = smem_to_u32(smc);
    const int tid  = threadIdx.x;
    const int wid  = tid >> 5;
    const int lane = tid & 31;
    const int warp_m = (wid & 3) * 32;
    const int warp_n = (wid >> 2) * 64;
    const int row0 = blockIdx.y * 128;
    const int col0 = blockIdx.x * 128;

    float C[2][8][4];
    #pragma unroll
    for (int mi = 0; mi < 2; mi++)
        #pragma unroll
        for (int nf = 0; nf < 8; nf++)
            #pragma unroll
            for (int e = 0; e < 4; e++) C[mi][nf][e] = 0.f;

    const int r_ld[2]  = { tid >> 2, (256 + tid) >> 2 };
    const int cc_ld    = tid & 3;
    const uint32_t so_ld[2] = {
        (uint32_t)(r_ld[0] * 80 + cc_ld * 16),
        (uint32_t)(r_ld[1] * 80 + cc_ld * 16)
    };

    float4 pa_hi[2], pa_lo[2], pb_hi[2], pb_lo[2];

    #pragma unroll
    for (int l = 0; l < 2; l++) {
        size_t ga = (size_t)(row0 + r_ld[l]) * E_ + cc_ld * 8;
        size_t gb = (size_t)(col0 + r_ld[l]) * E_ + cc_ld * 8;
        pa_hi[l] = *(const float4*)(Ahi + ga);
        pa_lo[l] = *(const float4*)(Alo + ga);
        pb_hi[l] = *(const float4*)(Bhi + gb);
        pb_lo[l] = *(const float4*)(Blo + gb);
    }
    #pragma unroll
    for (int l = 0; l < 2; l++) {
        *(float4*)(smc + 0*TILEB + so_ld[l]) = pa_hi[l];
        *(float4*)(smc + 1*TILEB + so_ld[l]) = pa_lo[l];
        *(float4*)(smc + 2*TILEB + so_ld[l]) = pb_hi[l];
        *(float4*)(smc + 3*TILEB + so_ld[l]) = pb_lo[l];
    }
    __syncthreads();

    const int NCH = E_ / KC;   // 32

    #pragma unroll 1
    for (int c = 0; c < NCH; c++) {
        const int p = c & 1;

        if (c + 1 < NCH) {
            const int k0 = (c + 1) * KC;
            #pragma unroll
            for (int l = 0; l < 2; l++) {
                size_t ga = (size_t)(row0 + r_ld[l]) * E_ + k0 + cc_ld * 8;
                size_t gb = (size_t)(col0 + r_ld[l]) * E_ + k0 + cc_ld * 8;
                pa_hi[l] = *(const float4*)(Ahi + ga);
                pa_lo[l] = *(const float4*)(Alo + ga);
                pb_hi[l] = *(const float4*)(Bhi + gb);
                pb_lo[l] = *(const float4*)(Blo + gb);
            }
        }

        const uint32_t bAhi = sb + p * BUFB + 0 * TILEB;
        const uint32_t bAlo = sb + p * BUFB + 1 * TILEB;
        const uint32_t bBhi = sb + p * BUFB + 2 * TILEB;
        const uint32_t bBlo = sb + p * BUFB + 3 * TILEB;

        #pragma unroll
        for (int ki = 0; ki < 2; ki++) {
            const int kf = ki * 16;
            uint32_t ah[2][4], al[2][4];
            {
                const uint32_t acol = (uint32_t)((kf + ((lane >> 4) << 3)) * 2);
                #pragma unroll
                for (int mi = 0; mi < 2; mi++) {
                    uint32_t ao = (uint32_t)((warp_m + mi * 16 + (lane & 15)) * 80) + acol;
                    ldsm_x4(ah[mi][0], ah[mi][1], ah[mi][2], ah[mi][3], bAhi + ao);
                    ldsm_x4(al[mi][0], al[mi][1], al[mi][2], al[mi][3], bAlo + ao);
                }
            }
            const uint32_t brow_off = (uint32_t)((lane & 7) + ((lane >> 4) & 1) * 8);
            const uint32_t bcol     = (uint32_t)((kf + ((lane >> 3) & 1) * 8) * 2);
            #pragma unroll
            for (int nj = 0; nj < 4; nj++) {
                uint32_t bo = (uint32_t)((warp_n + nj * 16 + brow_off) * 80) + bcol;
                uint32_t bh0, bh1, bh2, bh3, bl0, bl1, bl2, bl3;
                ldsm_x4(bh0, bh1, bh2, bh3, bBhi + bo);
                ldsm_x4(bl0, bl1, bl2, bl3, bBlo + bo);
                #pragma unroll
                for (int mi = 0; mi < 2; mi++) {
                    float* c0 = C[mi][nj * 2];
                    float* c1 = C[mi][nj * 2 + 1];
                    mma_bf16(c0, ah[mi][0], ah[mi][1], ah[mi][2], ah[mi][3], bh0, bh1);
                    mma_bf16(c0, al[mi][0], al[mi][1], al[mi][2], al[mi][3], bh0, bh1);
                    mma_bf16(c0, ah[mi][0], ah[mi][1], ah[mi][2], ah[mi][3], bl0, bl1);
                    mma_bf16(c1, ah[mi][0], ah[mi][1], ah[mi][2], ah[mi][3], bh2, bh3);
                    mma_bf16(c1, al[mi][0], al[mi][1], al[mi][2], al[mi][3], bh2, bh3);
                    mma_bf16(c1, ah[mi][0], ah[mi][1], ah[mi][2], ah[mi][3], bl2, bl3);
                }
            }
        }

        if (c + 1 < NCH) {
            __syncthreads();
            const int q = (c + 1) & 1;
            #pragma unroll
            for (int l = 0; l < 2; l++) {
                *(float4*)(smc + q * BUFB + 0 * TILEB + so_ld[l]) = pa_hi[l];
                *(float4*)(smc + q * BUFB + 1 * TILEB + so_ld[l]) = pa_lo[l];
                *(float4*)(smc + q * BUFB + 2 * TILEB + so_ld[l]) = pb_hi[l];
                *(float4*)(smc + q * BUFB + 3 * TILEB + so_ld[l]) = pb_lo[l];
            }
            __syncthreads();
        }
    }

    // ---- epilogue ----
    if (mode == 0) {
        #pragma unroll
        for (int mi = 0; mi < 2; mi++) {
            #pragma unroll
            for (int half = 0; half < 2; half++) {
                int t = row0 + warp_m + mi * 16 + (lane >> 2) + half * 8;
                int bb = t >> 11;
                int ss = t & (S_ - 1);
                #pragma unroll
                for (int nf = 0; nf < 8; nf++) {
                    int f = col0 + warp_n + nf * 8 + (lane & 3) * 2;
                    int which = f >> 10;
                    int rem = f & 1023;
                    int h = rem >> 6;
                    int d = rem & 63;
                    float v0 = C[mi][nf][half * 2];
                    float v1 = C[mi][nf][half * 2 + 1];
                    if (which == 0) { v0 *= 0.125f; v1 *= 0.125f; }
                    uint32_t hi2, lo2;
                    split_pack(v0, v1, hi2, lo2);
                    __nv_bfloat16* dhi = (which == 0) ? g_qhi : ((which == 1) ? g_khi : g_vhi);
                    __nv_bfloat16* dlo = (which == 0) ? g_qlo : ((which == 1) ? g_klo : g_vlo);
                    size_t idx = (((size_t)(bb * H_ + h)) * S_ + ss) * D_ + d;
                    *(uint32_t*)(dhi + idx) = hi2;
                    *(uint32_t*)(dlo + idx) = lo2;
                }
            }
        }
    } else {
        #pragma unroll
        for (int mi = 0; mi < 2; mi++) {
            #pragma unroll
            for (int half = 0; half < 2; half++) {
                int r = row0 + warp_m + mi * 16 + (lane >> 2) + half * 8;
                #pragma unroll
                for (int nf = 0; nf < 8; nf++) {
                    int f = col0 + warp_n + nf * 8 + (lane & 3) * 2;
                    float2 v = make_float2(C[mi][nf][half * 2],
                                           C[mi][nf][half * 2 + 1]);
                    *(float2*)(Cplain + (size_t)r * E_ + f) = v;
                }
            }
        }
    }
}

// ---------------------------------------------------------------------------
// Flash attention (causal) on tensor cores, bf16 hi/lo split.
// CTA: 64 q-rows, 4 warps (16 rows each), kv blocks of 64. 128 threads.
// SMEM planes (stride 72 bf16 = 144 B): Qhi,Qlo,Khi,Klo,Vhi,Vlo.
// ---------------------------------------------------------------------------
#define LDT   144                    // bytes per smem row (72 bf16)
#define PL    (64*LDT)               // 9216 bytes per plane
#define ATTN_SMEM (6*PL)             // 55296

__global__ void __launch_bounds__(128) attn_mma_kernel()
{
    extern __shared__ char sma[];
    const uint32_t sb = smem_to_u32(sma);
    const uint32_t oQhi = 0,      oQlo = PL,     oKhi = 2*PL;
    const uint32_t oKlo = 3*PL,   oVhi = 4*PL,   oVlo = 5*PL;

    const int qb = (int)gridDim.x - 1 - (int)blockIdx.x;  // longest-first
    const int bh = blockIdx.y;
    const int bb = bh >> 4;
    const int hh = bh & 15;
    const int tid  = threadIdx.x;
    const int wid  = tid >> 5;
    const int lane = tid & 31;
    const int warp_m = wid * 16;

    const __nv_bfloat16* Qh = g_qhi + ((size_t)bh * S_ + qb * 64) * D_;
    const __nv_bfloat16* Ql = g_qlo + ((size_t)bh * S_ + qb * 64) * D_;

    // ---- load Q tile (hi/lo) ----
    #pragma unroll
    for (int l = 0; l < 4; l++) {
        int idx = l * 128 + tid;         // 512 float4 slots
        int r  = idx >> 3;
        int dc = (idx & 7) * 8;
        uint32_t so = (uint32_t)(r * LDT + dc * 2);
        *(float4*)(sma + oQhi + so) = *(const float4*)(Qh + r * D_ + dc);
        *(float4*)(sma + oQlo + so) = *(const float4*)(Ql + r * D_ + dc);
    }
    __syncthreads();

    // ---- preload Q fragments ----
    uint32_t aqh[4][4], aql[4][4];
    {
        uint32_t ao = (uint32_t)((warp_m + (lane & 15)) * LDT);
        #pragma unroll
        for (int ki = 0; ki < 4; ki++) {
            uint32_t col = (uint32_t)((ki * 16 + (lane >> 4) * 8) * 2);
            ldsm_x4(aqh[ki][0], aqh[ki][1], aqh[ki][2], aqh[ki][3], sb + oQhi + ao + col);
            ldsm_x4(aql[ki][0], aql[ki][1], aql[ki][2], aql[ki][3], sb + oQlo + ao + col);
        }
    }

    float m[2]  = {-1e30f, -1e30f};
    float lsum[2] = {0.f, 0.f};
    float o[8][4];
    #pragma unroll
    for (int nf = 0; nf < 8; nf++)
        #pragma unroll
        for (int e = 0; e < 4; e++) o[nf][e] = 0.f;

    const __nv_bfloat16* Khb = g_khi + (size_t)bh * S_ * D_;
    const __nv_bfloat16* Klb = g_klo + (size_t)bh * S_ * D_;
    const __nv_bfloat16* Vhb = g_vhi + (size_t)bh * S_ * D_;
    const __nv_bfloat16* Vlb = g_vlo + (size_t)bh * S_ * D_;

    #pragma unroll 1
    for (int kb = 0; kb <= qb; kb++) {
        __syncthreads();   // previous iteration's ldmatrix reads done

        // ---- load K,V tiles (hi/lo) ----
        {
            const size_t base = (size_t)(kb * 64) * D_;
            #pragma unroll
            for (int l = 0; l < 4; l++) {
                int idx = l * 128 + tid;
                int r  = idx >> 3;
                int dc = (idx & 7) * 8;
                uint32_t so = (uint32_t)(r * LDT + dc * 2);
                size_t go = base + r * D_ + dc;
                *(float4*)(sma + oKhi + so) = *(const float4*)(Khb + go);
                *(float4*)(sma + oKlo + so) = *(const float4*)(Klb + go);
                *(float4*)(sma + oVhi + so) = *(const float4*)(Vhb + go);
                *(float4*)(sma + oVlo + so) = *(const float4*)(Vlb + go);
            }
        }
        __syncthreads();

        // ---- scores S = Q . K^T (3-pass hi/lo) ----
        float s[8][4];
        #pragma unroll
        for (int nf = 0; nf < 8; nf++)
            #pragma unroll
            for (int e = 0; e < 4; e++) s[nf][e] = 0.f;

        #pragma unroll
        for (int ki = 0; ki < 4; ki++) {
            const uint32_t ro = (uint32_t)((lane & 7) + ((lane >> 4) & 1) * 8);
            const uint32_t co = (uint32_t)((ki * 16 + ((lane >> 3) & 1) * 8) * 2);
            #pragma unroll
            for (int nj = 0; nj < 4; nj++) {
                uint32_t ad = (uint32_t)((nj * 16 + ro) * LDT) + co;
                uint32_t kh0, kh1, kh2, kh3, kl0, kl1, kl2, kl3;
                ldsm_x4(kh0, kh1, kh2, kh3, sb + oKhi + ad);
                ldsm_x4(kl0, kl1, kl2, kl3, sb + oKlo + ad);
                float* c0 = s[nj * 2];
                float* c1 = s[nj * 2 + 1];
                mma_bf16(c0, aqh[ki][0], aqh[ki][1], aqh[ki][2], aqh[ki][3], kh0, kh1);
                mma_bf16(c0, aql[ki][0], aql[ki][1], aql[ki][2], aql[ki][3], kh0, kh1);
                mma_bf16(c0, aqh[ki][0], aqh[ki][1], aqh[ki][2], aqh[ki][3], kl0, kl1);
                mma_bf16(c1, aqh[ki][0], aqh[ki][1], aqh[ki][2], aqh[ki][3], kh2, kh3);
                mma_bf16(c1, aql[ki][0], aql[ki][1], aql[ki][2], aql[ki][3], kh2, kh3);
                mma_bf16(c1, aqh[ki][0], aqh[ki][1], aqh[ki][2], aqh[ki][3], kl2, kl3);
            }
        }

        // ---- causal mask (diagonal block only) ----
        if (kb == qb) {
            const int qrow0 = qb * 64 + warp_m + (lane >> 2);
            #pragma unroll
            for (int nf = 0; nf < 8; nf++) {
                int kcol = kb * 64 + nf * 8 + (lane & 3) * 2;
                #pragma unroll
                for (int e = 0; e < 4; e++) {
                    int q = qrow0 + (e >> 1) * 8;
                    int kv = kcol + (e & 1);
                    if (kv > q) s[nf][e] = -1e30f;
                }
            }
        }

        // ---- online softmax (per row-half) ----
        #pragma unroll
        for (int h = 0; h < 2; h++) {
            float rmax = -1e30f;
            #pragma unroll
            for (int nf = 0; nf < 8; nf++) {
                rmax = fmaxf(rmax, s[nf][2*h]);
                rmax = fmaxf(rmax, s[nf][2*h+1]);
            }
            rmax = fmaxf(rmax, __shfl_xor_sync(0xffffffffu, rmax, 1));
            rmax = fmaxf(rmax, __shfl_xor_sync(0xffffffffu, rmax, 2));

            float mnew = fmaxf(m[h], rmax);
            float corr = __expf(m[h] - mnew);
            m[h] = mnew;

            float rsum = 0.f;
            #pragma unroll
            for (int nf = 0; nf < 8; nf++) {
                float p0 = __expf(s[nf][2*h]   - mnew);
                float p1 = __expf(s[nf][2*h+1] - mnew);
                s[nf][2*h]   = p0;
                s[nf][2*h+1] = p1;
                rsum += p0 + p1;
            }
            rsum += __shfl_xor_sync(0xffffffffu, rsum, 1);
            rsum += __shfl_xor_sync(0xffffffffu, rsum, 2);
            lsum[h] = lsum[h] * corr + rsum;

            #pragma unroll
            for (int nf = 0; nf < 8; nf++) {
                o[nf][2*h]   *= corr;
                o[nf][2*h+1] *= corr;
            }
        }

        // ---- O += P . V (P from regs, V via trans ldmatrix, 3-pass) ----
        #pragma unroll
        for (int ki = 0; ki < 4; ki++) {
            uint32_t aph[4], apl[4];
            split_pack(s[2*ki][0],   s[2*ki][1],   aph[0], apl[0]);
            split_pack(s[2*ki][2],   s[2*ki][3],   aph[1], apl[1]);
            split_pack(s[2*ki+1][0], s[2*ki+1][1], aph[2], apl[2]);
            split_pack(s[2*ki+1][2], s[2*ki+1][3], aph[3], apl[3]);

            const uint32_t ro = (uint32_t)((ki * 16 + (lane & 7) + ((lane >> 3) & 1) * 8) * LDT);
            const uint32_t cbase = (uint32_t)(((lane >> 4) & 1) * 8 * 2);
            #pragma unroll
            for (int nj = 0; nj < 4; nj++) {
                uint32_t ad = ro + cbase + (uint32_t)(nj * 16 * 2);
                uint32_t vh0, vh1, vh2, vh3, vl0, vl1, vl2, vl3;
                ldsm_x4_trans(vh0, vh1, vh2, vh3, sb + oVhi + ad);
                ldsm_x4_trans(vl0, vl1, vl2, vl3, sb + oVlo + ad);
                float* c0 = o[nj * 2];
                float* c1 = o[nj * 2 + 1];
                mma_bf16(c0, aph[0], aph[1], aph[2], aph[3], vh0, vh1);
                mma_bf16(c0, apl[0], apl[1], apl[2], apl[3], vh0, vh1);
                mma_bf16(c0, aph[0], aph[1], aph[2], aph[3], vl0, vl1);
                mma_bf16(c1, aph[0], aph[1], aph[2], aph[3], vh2, vh3);
                mma_bf16(c1, apl[0], apl[1], apl[2], apl[3], vh2, vh3);
                mma_bf16(c1, aph[0], aph[1], aph[2], aph[3], vl2, vl3);
            }
        }
    }

    // ---- epilogue: O / l, split to bf16 hi/lo planes [B,S,E] ----
    #pragma unroll
    for (int h = 0; h < 2; h++) {
        float inv = 1.0f / lsum[h];
        int r = warp_m + (lane >> 2) + h * 8;
        size_t t = (size_t)(bb * S_ + qb * 64 + r);
        #pragma unroll
        for (int nf = 0; nf < 8; nf++) {
            int dcol = hh * 64 + nf * 8 + (lane & 3) * 2;
            uint32_t hi2, lo2;
            split_pack(o[nf][2*h] * inv, o[nf][2*h+1] * inv, hi2, lo2);
            *(uint32_t*)(g_ohi + t * E_ + dcol) = hi2;
            *(uint32_t*)(g_olo + t * E_ + dcol) = lo2;
        }
    }
}

// ---------------------------------------------------------------------------
extern "C" void kernel_launch(void* const* d_in, const int* in_sizes, int n_in,
                              void* d_out, int out_size)
{
    const float* x     = (const float*)d_in[0];   // [B,S,E]
    const float* w_qkv = (const float*)d_in[1];   // [3E,E]
    const float* w_out = (const float*)d_in[2];   // [E,E]
    float* out = (float*)d_out;                   // [B,S,E]

    __nv_bfloat16 *xhi, *xlo, *wqhi, *wqlo, *wohi, *wolo, *ohi, *olo;
    cudaGetSymbolAddress((void**)&xhi,  g_xhi);
    cudaGetSymbolAddress((void**)&xlo,  g_xlo);
    cudaGetSymbolAddress((void**)&wqhi, g_wqhi);
    cudaGetSymbolAddress((void**)&wqlo, g_wqlo);
    cudaGetSymbolAddress((void**)&wohi, g_wohi);
    cudaGetSymbolAddress((void**)&wolo, g_wolo);
    cudaGetSymbolAddress((void**)&ohi,  g_ohi);
    cudaGetSymbolAddress((void**)&olo,  g_olo);

    static bool attr_set = false;
    if (!attr_set) {
        cudaFuncSetAttribute(mma_gemm_kernel,
                             cudaFuncAttributeMaxDynamicSharedMemorySize,
                             GEMM_SMEM);
        cudaFuncSetAttribute(attn_mma_kernel,
                             cudaFuncAttributeMaxDynamicSharedMemorySize,
                             ATTN_SMEM);
        attr_set = true;
    }

    // 0) fp32 -> bf16 hi/lo splits for X and weights
    {
        int n4 = NT * E_ / 4;
        split_kernel<<<n4 / 256, 256>>>(x, xhi, xlo, n4);
        n4 = F3 * E_ / 4;
        split_kernel<<<n4 / 256, 256>>>(w_qkv, wqhi, wqlo, n4);
        n4 = E_ * E_ / 4;
        split_kernel<<<n4 / 256, 256>>>(w_out, wohi, wolo, n4);
    }

    // 1) QKV projection (tensor cores) -> bf16 hi/lo q/k/v planes
    {
        dim3 grid(F3 / 128, NT / 128);   // (24, 32)
        mma_gemm_kernel<<<grid, 256, GEMM_SMEM>>>(
            xhi, xlo, wqhi, wqlo, nullptr, 0);
    }

    // 2) Flash attention (causal, tensor cores) -> bf16 hi/lo O planes
    {
        dim3 grid(S_ / 64, B_ * H_);     // (32, 32)
        attn_mma_kernel<<<grid, 128, ATTN_SMEM>>>();
    }

    // 3) Output projection (tensor cores) -> fp32 out
    {
        dim3 grid(E_ / 128, NT / 128);   // (8, 32)
        mma_gemm_kernel<<<grid, 256, GEMM_SMEM>>>(
            ohi, olo, wohi, wolo, out, 1);
    }
}

// round 5
// speedup vs baseline: 3.0244x; 1.2153x over previous
#include <cuda_runtime.h>
#include <cuda_bf16.h>
#include <cstdint>
#include <math.h>

// Problem constants
#define B_  2
#define S_  2048
#define E_  1024
#define H_  16
#define D_  64
#define NT  (B_*S_)      // 4096 tokens
#define F3  (3*E_)       // 3072 qkv features

// ---------------------------------------------------------------------------
// Device-global scratch (no allocation allowed)
// ---------------------------------------------------------------------------
#define QKV_ELEMS ((size_t)B_*H_*S_*D_)
__device__ __nv_bfloat16 g_qhi[QKV_ELEMS], g_qlo[QKV_ELEMS];
__device__ __nv_bfloat16 g_khi[QKV_ELEMS], g_klo[QKV_ELEMS];
__device__ __nv_bfloat16 g_vhi[QKV_ELEMS], g_vlo[QKV_ELEMS];

__device__ __nv_bfloat16 g_xhi[(size_t)NT*E_],  g_xlo[(size_t)NT*E_];
__device__ __nv_bfloat16 g_wqhi[(size_t)F3*E_], g_wqlo[(size_t)F3*E_];
__device__ __nv_bfloat16 g_wohi[(size_t)E_*E_], g_wolo[(size_t)E_*E_];
__device__ __nv_bfloat16 g_ohi[(size_t)NT*E_],  g_olo[(size_t)NT*E_];

// ---------------------------------------------------------------------------
// Warp-level tensor-core helpers (portable PTX: sm_80+, assembles on sm_103)
// ---------------------------------------------------------------------------
__device__ __forceinline__ uint32_t smem_to_u32(const void* p) {
    uint32_t a;
    asm("{ .reg .u64 t; cvta.to.shared.u64 t, %1; cvt.u32.u64 %0, t; }"
        : "=r"(a) : "l"(p));
    return a;
}

__device__ __forceinline__ void ldsm_x4(uint32_t& r0, uint32_t& r1,
                                        uint32_t& r2, uint32_t& r3,
                                        uint32_t addr) {
    asm volatile("ldmatrix.sync.aligned.m8n8.x4.shared.b16 {%0,%1,%2,%3}, [%4];"
        : "=r"(r0), "=r"(r1), "=r"(r2), "=r"(r3) : "r"(addr));
}
__device__ __forceinline__ void ldsm_x4_trans(uint32_t& r0, uint32_t& r1,
                                              uint32_t& r2, uint32_t& r3,
                                              uint32_t addr) {
    asm volatile("ldmatrix.sync.aligned.m8n8.x4.trans.shared.b16 {%0,%1,%2,%3}, [%4];"
        : "=r"(r0), "=r"(r1), "=r"(r2), "=r"(r3) : "r"(addr));
}

__device__ __forceinline__ void mma_bf16(float c[4],
                                         uint32_t a0, uint32_t a1,
                                         uint32_t a2, uint32_t a3,
                                         uint32_t b0, uint32_t b1) {
    asm volatile(
        "mma.sync.aligned.m16n8k16.row.col.f32.bf16.bf16.f32 "
        "{%0,%1,%2,%3}, {%4,%5,%6,%7}, {%8,%9}, {%0,%1,%2,%3};"
        : "+f"(c[0]), "+f"(c[1]), "+f"(c[2]), "+f"(c[3])
        : "r"(a0), "r"(a1), "r"(a2), "r"(a3), "r"(b0), "r"(b1));
}

__device__ __forceinline__ void cp16(uint32_t dst, const void* src) {
    asm volatile("cp.async.cg.shared.global [%0], [%1], 16;"
        :: "r"(dst), "l"(src) : "memory");
}
#define CP_COMMIT() asm volatile("cp.async.commit_group;" ::: "memory")
#define CP_WAIT(N)  asm volatile("cp.async.wait_group %0;" :: "n"(N) : "memory")

// pack two fp32 into bf16x2 (hi) and residual bf16x2 (lo)
__device__ __forceinline__ void split_pack(float p0, float p1,
                                           uint32_t& hi2, uint32_t& lo2) {
    __nv_bfloat162 h = __floats2bfloat162_rn(p0, p1);
    float r0 = p0 - __bfloat162float(h.x);
    float r1 = p1 - __bfloat162float(h.y);
    __nv_bfloat162 l = __floats2bfloat162_rn(r0, r1);
    hi2 = *(uint32_t*)&h;
    lo2 = *(uint32_t*)&l;
}

// ---------------------------------------------------------------------------
// fp32 -> bf16 hi/lo split
// ---------------------------------------------------------------------------
__global__ void __launch_bounds__(256) split_kernel(
    const float* __restrict__ in,
    __nv_bfloat16* __restrict__ hi, __nv_bfloat16* __restrict__ lo, int n4)
{
    int i = blockIdx.x * blockDim.x + threadIdx.x;
    if (i >= n4) return;
    float4 v = ((const float4*)in)[i];
    float f[4] = {v.x, v.y, v.z, v.w};
    unsigned short hs[4], ls[4];
    #pragma unroll
    for (int j = 0; j < 4; j++) {
        __nv_bfloat16 h = __float2bfloat16(f[j]);
        __nv_bfloat16 l = __float2bfloat16(f[j] - __bfloat162float(h));
        hs[j] = *(unsigned short*)&h;
        ls[j] = *(unsigned short*)&l;
    }
    ((ushort4*)hi)[i] = make_ushort4(hs[0], hs[1], hs[2], hs[3]);
    ((ushort4*)lo)[i] = make_ushort4(ls[0], ls[1], ls[2], ls[3]);
}

// ---------------------------------------------------------------------------
// bf16-split mma.sync GEMM: C[M,N] = A[M,K] * B[N,K]^T (fp32-equivalent).
// CTA tile 128x128, K-chunk 32, 8 warps (4m x 2n), warp tile 32x64.
// cp.async double-buffered SMEM (no register prefetch -> 2 CTAs/SM).
// mode 0: QKV — split results into g_{q,k,v}{hi,lo} planes (Q scaled 0.125)
// mode 1: plain fp32 store to Cplain.
// ---------------------------------------------------------------------------
#define KC    32
#define LDA   40
#define TILEB (128*LDA*2)             // 10240 bytes per tile
#define BUFB  (4*TILEB)               // 40960 bytes (Ahi,Alo,Bhi,Blo)
#define GEMM_SMEM (2*BUFB)            // 81920

__global__ void __launch_bounds__(256, 2) mma_gemm_kernel(
    const __nv_bfloat16* __restrict__ Ahi, const __nv_bfloat16* __restrict__ Alo,
    const __nv_bfloat16* __restrict__ Bhi, const __nv_bfloat16* __restrict__ Blo,
    float* __restrict__ Cplain, int mode)
{
    extern __shared__ char smc[];
    const uint32_t sb = smem_to_u32(smc);
    const int tid  = threadIdx.x;
    const int wid  = tid >> 5;
    const int lane = tid & 31;
    const int warp_m = (wid & 3) * 32;
    const int warp_n = (wid >> 2) * 64;
    const int row0 = blockIdx.y * 128;
    const int col0 = blockIdx.x * 128;

    float C[2][8][4];
    #pragma unroll
    for (int mi = 0; mi < 2; mi++)
        #pragma unroll
        for (int nf = 0; nf < 8; nf++)
            #pragma unroll
            for (int e = 0; e < 4; e++) C[mi][nf][e] = 0.f;

    const int r_ld[2]  = { tid >> 2, (256 + tid) >> 2 };
    const int cc_ld    = tid & 3;
    const uint32_t so_ld[2] = {
        (uint32_t)(r_ld[0] * 80 + cc_ld * 16),
        (uint32_t)(r_ld[1] * 80 + cc_ld * 16)
    };

    const int NCH = E_ / KC;   // 32

    // ---- issue chunk 0 into stage 0 ----
    {
        const uint32_t base = sb;
        #pragma unroll
        for (int l = 0; l < 2; l++) {
            size_t ga = (size_t)(row0 + r_ld[l]) * E_ + cc_ld * 8;
            size_t gb = (size_t)(col0 + r_ld[l]) * E_ + cc_ld * 8;
            cp16(base + 0*TILEB + so_ld[l], Ahi + ga);
            cp16(base + 1*TILEB + so_ld[l], Alo + ga);
            cp16(base + 2*TILEB + so_ld[l], Bhi + gb);
            cp16(base + 3*TILEB + so_ld[l], Blo + gb);
        }
        CP_COMMIT();
    }

    #pragma unroll 1
    for (int c = 0; c < NCH; c++) {
        const int p = c & 1;

        // issue chunk c+1 into the other stage
        if (c + 1 < NCH) {
            const int k0 = (c + 1) * KC;
            const uint32_t base = sb + (p ^ 1) * BUFB;
            #pragma unroll
            for (int l = 0; l < 2; l++) {
                size_t ga = (size_t)(row0 + r_ld[l]) * E_ + k0 + cc_ld * 8;
                size_t gb = (size_t)(col0 + r_ld[l]) * E_ + k0 + cc_ld * 8;
                cp16(base + 0*TILEB + so_ld[l], Ahi + ga);
                cp16(base + 1*TILEB + so_ld[l], Alo + ga);
                cp16(base + 2*TILEB + so_ld[l], Bhi + gb);
                cp16(base + 3*TILEB + so_ld[l], Blo + gb);
            }
            CP_COMMIT();
            CP_WAIT(1);       // stage p complete (one group still in flight)
        } else {
            CP_WAIT(0);       // all complete
        }
        __syncthreads();

        // ---- compute from stage p ----
        const uint32_t bAhi = sb + p * BUFB + 0 * TILEB;
        const uint32_t bAlo = sb + p * BUFB + 1 * TILEB;
        const uint32_t bBhi = sb + p * BUFB + 2 * TILEB;
        const uint32_t bBlo = sb + p * BUFB + 3 * TILEB;

        #pragma unroll
        for (int ki = 0; ki < 2; ki++) {
            const int kf = ki * 16;
            uint32_t ah[2][4], al[2][4];
            {
                const uint32_t acol = (uint32_t)((kf + ((lane >> 4) << 3)) * 2);
                #pragma unroll
                for (int mi = 0; mi < 2; mi++) {
                    uint32_t ao = (uint32_t)((warp_m + mi * 16 + (lane & 15)) * 80) + acol;
                    ldsm_x4(ah[mi][0], ah[mi][1], ah[mi][2], ah[mi][3], bAhi + ao);
                    ldsm_x4(al[mi][0], al[mi][1], al[mi][2], al[mi][3], bAlo + ao);
                }
            }
            const uint32_t brow_off = (uint32_t)((lane & 7) + ((lane >> 4) & 1) * 8);
            const uint32_t bcol     = (uint32_t)((kf + ((lane >> 3) & 1) * 8) * 2);
            #pragma unroll
            for (int nj = 0; nj < 4; nj++) {
                uint32_t bo = (uint32_t)((warp_n + nj * 16 + brow_off) * 80) + bcol;
                uint32_t bh0, bh1, bh2, bh3, bl0, bl1, bl2, bl3;
                ldsm_x4(bh0, bh1, bh2, bh3, bBhi + bo);
                ldsm_x4(bl0, bl1, bl2, bl3, bBlo + bo);
                #pragma unroll
                for (int mi = 0; mi < 2; mi++) {
                    float* c0 = C[mi][nj * 2];
                    float* c1 = C[mi][nj * 2 + 1];
                    mma_bf16(c0, ah[mi][0], ah[mi][1], ah[mi][2], ah[mi][3], bh0, bh1);
                    mma_bf16(c0, al[mi][0], al[mi][1], al[mi][2], al[mi][3], bh0, bh1);
                    mma_bf16(c0, ah[mi][0], ah[mi][1], ah[mi][2], ah[mi][3], bl0, bl1);
                    mma_bf16(c1, ah[mi][0], ah[mi][1], ah[mi][2], ah[mi][3], bh2, bh3);
                    mma_bf16(c1, al[mi][0], al[mi][1], al[mi][2], al[mi][3], bh2, bh3);
                    mma_bf16(c1, ah[mi][0], ah[mi][1], ah[mi][2], ah[mi][3], bl2, bl3);
                }
            }
        }

        // protect stage p: next iteration's cp.async writes into it
        if (c + 1 < NCH) __syncthreads();
    }

    // ---- epilogue ----
    if (mode == 0) {
        #pragma unroll
        for (int mi = 0; mi < 2; mi++) {
            #pragma unroll
            for (int half = 0; half < 2; half++) {
                int t = row0 + warp_m + mi * 16 + (lane >> 2) + half * 8;
                int bb = t >> 11;
                int ss = t & (S_ - 1);
                #pragma unroll
                for (int nf = 0; nf < 8; nf++) {
                    int f = col0 + warp_n + nf * 8 + (lane & 3) * 2;
                    int which = f >> 10;
                    int rem = f & 1023;
                    int h = rem >> 6;
                    int d = rem & 63;
                    float v0 = C[mi][nf][half * 2];
                    float v1 = C[mi][nf][half * 2 + 1];
                    if (which == 0) { v0 *= 0.125f; v1 *= 0.125f; }
                    uint32_t hi2, lo2;
                    split_pack(v0, v1, hi2, lo2);
                    __nv_bfloat16* dhi = (which == 0) ? g_qhi : ((which == 1) ? g_khi : g_vhi);
                    __nv_bfloat16* dlo = (which == 0) ? g_qlo : ((which == 1) ? g_klo : g_vlo);
                    size_t idx = (((size_t)(bb * H_ + h)) * S_ + ss) * D_ + d;
                    *(uint32_t*)(dhi + idx) = hi2;
                    *(uint32_t*)(dlo + idx) = lo2;
                }
            }
        }
    } else {
        #pragma unroll
        for (int mi = 0; mi < 2; mi++) {
            #pragma unroll
            for (int half = 0; half < 2; half++) {
                int r = row0 + warp_m + mi * 16 + (lane >> 2) + half * 8;
                #pragma unroll
                for (int nf = 0; nf < 8; nf++) {
                    int f = col0 + warp_n + nf * 8 + (lane & 3) * 2;
                    float2 v = make_float2(C[mi][nf][half * 2],
                                           C[mi][nf][half * 2 + 1]);
                    *(float2*)(Cplain + (size_t)r * E_ + f) = v;
                }
            }
        }
    }
}

// ---------------------------------------------------------------------------
// Flash attention (causal) on tensor cores, bf16 hi/lo split (same as R4).
// CTA: 64 q-rows, 4 warps, kv blocks of 64. 128 threads.
// ---------------------------------------------------------------------------
#define LDT   144                    // bytes per smem row (72 bf16)
#define PL    (64*LDT)               // 9216 bytes per plane
#define ATTN_SMEM (6*PL)             // 55296

__global__ void __launch_bounds__(128) attn_mma_kernel()
{
    extern __shared__ char sma[];
    const uint32_t sb = smem_to_u32(sma);
    const uint32_t oQhi = 0,      oQlo = PL,     oKhi = 2*PL;
    const uint32_t oKlo = 3*PL,   oVhi = 4*PL,   oVlo = 5*PL;

    const int qb = (int)gridDim.x - 1 - (int)blockIdx.x;  // longest-first
    const int bh = blockIdx.y;
    const int bb = bh >> 4;
    const int hh = bh & 15;
    const int tid  = threadIdx.x;
    const int wid  = tid >> 5;
    const int lane = tid & 31;
    const int warp_m = wid * 16;

    const __nv_bfloat16* Qh = g_qhi + ((size_t)bh * S_ + qb * 64) * D_;
    const __nv_bfloat16* Ql = g_qlo + ((size_t)bh * S_ + qb * 64) * D_;

    #pragma unroll
    for (int l = 0; l < 4; l++) {
        int idx = l * 128 + tid;
        int r  = idx >> 3;
        int dc = (idx & 7) * 8;
        uint32_t so = (uint32_t)(r * LDT + dc * 2);
        *(float4*)(sma + oQhi + so) = *(const float4*)(Qh + r * D_ + dc);
        *(float4*)(sma + oQlo + so) = *(const float4*)(Ql + r * D_ + dc);
    }
    __syncthreads();

    uint32_t aqh[4][4], aql[4][4];
    {
        uint32_t ao = (uint32_t)((warp_m + (lane & 15)) * LDT);
        #pragma unroll
        for (int ki = 0; ki < 4; ki++) {
            uint32_t col = (uint32_t)((ki * 16 + (lane >> 4) * 8) * 2);
            ldsm_x4(aqh[ki][0], aqh[ki][1], aqh[ki][2], aqh[ki][3], sb + oQhi + ao + col);
            ldsm_x4(aql[ki][0], aql[ki][1], aql[ki][2], aql[ki][3], sb + oQlo + ao + col);
        }
    }

    float m[2]  = {-1e30f, -1e30f};
    float lsum[2] = {0.f, 0.f};
    float o[8][4];
    #pragma unroll
    for (int nf = 0; nf < 8; nf++)
        #pragma unroll
        for (int e = 0; e < 4; e++) o[nf][e] = 0.f;

    const __nv_bfloat16* Khb = g_khi + (size_t)bh * S_ * D_;
    const __nv_bfloat16* Klb = g_klo + (size_t)bh * S_ * D_;
    const __nv_bfloat16* Vhb = g_vhi + (size_t)bh * S_ * D_;
    const __nv_bfloat16* Vlb = g_vlo + (size_t)bh * S_ * D_;

    #pragma unroll 1
    for (int kb = 0; kb <= qb; kb++) {
        __syncthreads();

        {
            const size_t base = (size_t)(kb * 64) * D_;
            #pragma unroll
            for (int l = 0; l < 4; l++) {
                int idx = l * 128 + tid;
                int r  = idx >> 3;
                int dc = (idx & 7) * 8;
                uint32_t so = (uint32_t)(r * LDT + dc * 2);
                size_t go = base + r * D_ + dc;
                *(float4*)(sma + oKhi + so) = *(const float4*)(Khb + go);
                *(float4*)(sma + oKlo + so) = *(const float4*)(Klb + go);
                *(float4*)(sma + oVhi + so) = *(const float4*)(Vhb + go);
                *(float4*)(sma + oVlo + so) = *(const float4*)(Vlb + go);
            }
        }
        __syncthreads();

        float s[8][4];
        #pragma unroll
        for (int nf = 0; nf < 8; nf++)
            #pragma unroll
            for (int e = 0; e < 4; e++) s[nf][e] = 0.f;

        #pragma unroll
        for (int ki = 0; ki < 4; ki++) {
            const uint32_t ro = (uint32_t)((lane & 7) + ((lane >> 4) & 1) * 8);
            const uint32_t co = (uint32_t)((ki * 16 + ((lane >> 3) & 1) * 8) * 2);
            #pragma unroll
            for (int nj = 0; nj < 4; nj++) {
                uint32_t ad = (uint32_t)((nj * 16 + ro) * LDT) + co;
                uint32_t kh0, kh1, kh2, kh3, kl0, kl1, kl2, kl3;
                ldsm_x4(kh0, kh1, kh2, kh3, sb + oKhi + ad);
                ldsm_x4(kl0, kl1, kl2, kl3, sb + oKlo + ad);
                float* c0 = s[nj * 2];
                float* c1 = s[nj * 2 + 1];
                mma_bf16(c0, aqh[ki][0], aqh[ki][1], aqh[ki][2], aqh[ki][3], kh0, kh1);
                mma_bf16(c0, aql[ki][0], aql[ki][1], aql[ki][2], aql[ki][3], kh0, kh1);
                mma_bf16(c0, aqh[ki][0], aqh[ki][1], aqh[ki][2], aqh[ki][3], kl0, kl1);
                mma_bf16(c1, aqh[ki][0], aqh[ki][1], aqh[ki][2], aqh[ki][3], kh2, kh3);
                mma_bf16(c1, aql[ki][0], aql[ki][1], aql[ki][2], aql[ki][3], kh2, kh3);
                mma_bf16(c1, aqh[ki][0], aqh[ki][1], aqh[ki][2], aqh[ki][3], kl2, kl3);
            }
        }

        if (kb == qb) {
            const int qrow0 = qb * 64 + warp_m + (lane >> 2);
            #pragma unroll
            for (int nf = 0; nf < 8; nf++) {
                int kcol = kb * 64 + nf * 8 + (lane & 3) * 2;
                #pragma unroll
                for (int e = 0; e < 4; e++) {
                    int q = qrow0 + (e >> 1) * 8;
                    int kv = kcol + (e & 1);
                    if (kv > q) s[nf][e] = -1e30f;
                }
            }
        }

        #pragma unroll
        for (int h = 0; h < 2; h++) {
            float rmax = -1e30f;
            #pragma unroll
            for (int nf = 0; nf < 8; nf++) {
                rmax = fmaxf(rmax, s[nf][2*h]);
                rmax = fmaxf(rmax, s[nf][2*h+1]);
            }
            rmax = fmaxf(rmax, __shfl_xor_sync(0xffffffffu, rmax, 1));
            rmax = fmaxf(rmax, __shfl_xor_sync(0xffffffffu, rmax, 2));

            float mnew = fmaxf(m[h], rmax);
            float corr = __expf(m[h] - mnew);
            m[h] = mnew;

            float rsum = 0.f;
            #pragma unroll
            for (int nf = 0; nf < 8; nf++) {
                float p0 = __expf(s[nf][2*h]   - mnew);
                float p1 = __expf(s[nf][2*h+1] - mnew);
                s[nf][2*h]   = p0;
                s[nf][2*h+1] = p1;
                rsum += p0 + p1;
            }
            rsum += __shfl_xor_sync(0xffffffffu, rsum, 1);
            rsum += __shfl_xor_sync(0xffffffffu, rsum, 2);
            lsum[h] = lsum[h] * corr + rsum;

            #pragma unroll
            for (int nf = 0; nf < 8; nf++) {
                o[nf][2*h]   *= corr;
                o[nf][2*h+1] *= corr;
            }
        }

        #pragma unroll
        for (int ki = 0; ki < 4; ki++) {
            uint32_t aph[4], apl[4];
            split_pack(s[2*ki][0],   s[2*ki][1],   aph[0], apl[0]);
            split_pack(s[2*ki][2],   s[2*ki][3],   aph[1], apl[1]);
            split_pack(s[2*ki+1][0], s[2*ki+1][1], aph[2], apl[2]);
            split_pack(s[2*ki+1][2], s[2*ki+1][3], aph[3], apl[3]);

            const uint32_t ro = (uint32_t)((ki * 16 + (lane & 7) + ((lane >> 3) & 1) * 8) * LDT);
            const uint32_t cbase = (uint32_t)(((lane >> 4) & 1) * 8 * 2);
            #pragma unroll
            for (int nj = 0; nj < 4; nj++) {
                uint32_t ad = ro + cbase + (uint32_t)(nj * 16 * 2);
                uint32_t vh0, vh1, vh2, vh3, vl0, vl1, vl2, vl3;
                ldsm_x4_trans(vh0, vh1, vh2, vh3, sb + oVhi + ad);
                ldsm_x4_trans(vl0, vl1, vl2, vl3, sb + oVlo + ad);
                float* c0 = o[nj * 2];
                float* c1 = o[nj * 2 + 1];
                mma_bf16(c0, aph[0], aph[1], aph[2], aph[3], vh0, vh1);
                mma_bf16(c0, apl[0], apl[1], apl[2], apl[3], vh0, vh1);
                mma_bf16(c0, aph[0], aph[1], aph[2], aph[3], vl0, vl1);
                mma_bf16(c1, aph[0], aph[1], aph[2], aph[3], vh2, vh3);
                mma_bf16(c1, apl[0], apl[1], apl[2], apl[3], vh2, vh3);
                mma_bf16(c1, aph[0], aph[1], aph[2], aph[3], vl2, vl3);
            }
        }
    }

    #pragma unroll
    for (int h = 0; h < 2; h++) {
        float inv = 1.0f / lsum[h];
        int r = warp_m + (lane >> 2) + h * 8;
        size_t t = (size_t)(bb * S_ + qb * 64 + r);
        #pragma unroll
        for (int nf = 0; nf < 8; nf++) {
            int dcol = hh * 64 + nf * 8 + (lane & 3) * 2;
            uint32_t hi2, lo2;
            split_pack(o[nf][2*h] * inv, o[nf][2*h+1] * inv, hi2, lo2);
            *(uint32_t*)(g_ohi + t * E_ + dcol) = hi2;
            *(uint32_t*)(g_olo + t * E_ + dcol) = lo2;
        }
    }
}

// ---------------------------------------------------------------------------
extern "C" void kernel_launch(void* const* d_in, const int* in_sizes, int n_in,
                              void* d_out, int out_size)
{
    const float* x     = (const float*)d_in[0];   // [B,S,E]
    const float* w_qkv = (const float*)d_in[1];   // [3E,E]
    const float* w_out = (const float*)d_in[2];   // [E,E]
    float* out = (float*)d_out;                   // [B,S,E]

    __nv_bfloat16 *xhi, *xlo, *wqhi, *wqlo, *wohi, *wolo, *ohi, *olo;
    cudaGetSymbolAddress((void**)&xhi,  g_xhi);
    cudaGetSymbolAddress((void**)&xlo,  g_xlo);
    cudaGetSymbolAddress((void**)&wqhi, g_wqhi);
    cudaGetSymbolAddress((void**)&wqlo, g_wqlo);
    cudaGetSymbolAddress((void**)&wohi, g_wohi);
    cudaGetSymbolAddress((void**)&wolo, g_wolo);
    cudaGetSymbolAddress((void**)&ohi,  g_ohi);
    cudaGetSymbolAddress((void**)&olo,  g_olo);

    static bool attr_set = false;
    if (!attr_set) {
        cudaFuncSetAttribute(mma_gemm_kernel,
                             cudaFuncAttributeMaxDynamicSharedMemorySize,
                             GEMM_SMEM);
        cudaFuncSetAttribute(attn_mma_kernel,
                             cudaFuncAttributeMaxDynamicSharedMemorySize,
                             ATTN_SMEM);
        attr_set = true;
    }

    // 0) fp32 -> bf16 hi/lo splits for X and weights
    {
        int n4 = NT * E_ / 4;
        split_kernel<<<n4 / 256, 256>>>(x, xhi, xlo, n4);
        n4 = F3 * E_ / 4;
        split_kernel<<<n4 / 256, 256>>>(w_qkv, wqhi, wqlo, n4);
        n4 = E_ * E_ / 4;
        split_kernel<<<n4 / 256, 256>>>(w_out, wohi, wolo, n4);
    }

    // 1) QKV projection (tensor cores) -> bf16 hi/lo q/k/v planes
    {
        dim3 grid(F3 / 128, NT / 128);   // (24, 32)
        mma_gemm_kernel<<<grid, 256, GEMM_SMEM>>>(
            xhi, xlo, wqhi, wqlo, nullptr, 0);
    }

    // 2) Flash attention (causal, tensor cores) -> bf16 hi/lo O planes
    {
        dim3 grid(S_ / 64, B_ * H_);     // (32, 32)
        attn_mma_kernel<<<grid, 128, ATTN_SMEM>>>();
    }

    // 3) Output projection (tensor cores) -> fp32 out
    {
        dim3 grid(E_ / 128, NT / 128);   // (8, 32)
        mma_gemm_kernel<<<grid, 256, GEMM_SMEM>>>(
            ohi, olo, wohi, wolo, out, 1);
    }
}

// round 6
// speedup vs baseline: 3.2583x; 1.0774x over previous
#include <cuda_runtime.h>
#include <cuda_bf16.h>
#include <cstdint>
#include <math.h>

// Problem constants
#define B_  2
#define S_  2048
#define E_  1024
#define H_  16
#define D_  64
#define NT  (B_*S_)      // 4096 tokens
#define F3  (3*E_)       // 3072 qkv features

// ---------------------------------------------------------------------------
// Device-global scratch (no allocation allowed)
// ---------------------------------------------------------------------------
#define QKV_ELEMS ((size_t)B_*H_*S_*D_)
__device__ __nv_bfloat16 g_qhi[QKV_ELEMS], g_qlo[QKV_ELEMS];
__device__ __nv_bfloat16 g_khi[QKV_ELEMS], g_klo[QKV_ELEMS];
__device__ __nv_bfloat16 g_vhi[QKV_ELEMS], g_vlo[QKV_ELEMS];

__device__ __nv_bfloat16 g_xhi[(size_t)NT*E_],  g_xlo[(size_t)NT*E_];
__device__ __nv_bfloat16 g_wqhi[(size_t)F3*E_], g_wqlo[(size_t)F3*E_];
__device__ __nv_bfloat16 g_wohi[(size_t)E_*E_], g_wolo[(size_t)E_*E_];
__device__ __nv_bfloat16 g_ohi[(size_t)NT*E_],  g_olo[(size_t)NT*E_];

// ---------------------------------------------------------------------------
// Warp-level tensor-core helpers (portable PTX: sm_80+, assembles on sm_103)
// ---------------------------------------------------------------------------
__device__ __forceinline__ uint32_t smem_to_u32(const void* p) {
    uint32_t a;
    asm("{ .reg .u64 t; cvta.to.shared.u64 t, %1; cvt.u32.u64 %0, t; }"
        : "=r"(a) : "l"(p));
    return a;
}

__device__ __forceinline__ void ldsm_x4(uint32_t& r0, uint32_t& r1,
                                        uint32_t& r2, uint32_t& r3,
                                        uint32_t addr) {
    asm volatile("ldmatrix.sync.aligned.m8n8.x4.shared.b16 {%0,%1,%2,%3}, [%4];"
        : "=r"(r0), "=r"(r1), "=r"(r2), "=r"(r3) : "r"(addr));
}
__device__ __forceinline__ void ldsm_x4_trans(uint32_t& r0, uint32_t& r1,
                                              uint32_t& r2, uint32_t& r3,
                                              uint32_t addr) {
    asm volatile("ldmatrix.sync.aligned.m8n8.x4.trans.shared.b16 {%0,%1,%2,%3}, [%4];"
        : "=r"(r0), "=r"(r1), "=r"(r2), "=r"(r3) : "r"(addr));
}

__device__ __forceinline__ void mma_bf16(float c[4],
                                         uint32_t a0, uint32_t a1,
                                         uint32_t a2, uint32_t a3,
                                         uint32_t b0, uint32_t b1) {
    asm volatile(
        "mma.sync.aligned.m16n8k16.row.col.f32.bf16.bf16.f32 "
        "{%0,%1,%2,%3}, {%4,%5,%6,%7}, {%8,%9}, {%0,%1,%2,%3};"
        : "+f"(c[0]), "+f"(c[1]), "+f"(c[2]), "+f"(c[3])
        : "r"(a0), "r"(a1), "r"(a2), "r"(a3), "r"(b0), "r"(b1));
}

__device__ __forceinline__ void cp16(uint32_t dst, const void* src) {
    asm volatile("cp.async.cg.shared.global [%0], [%1], 16;"
        :: "r"(dst), "l"(src) : "memory");
}
#define CP_COMMIT() asm volatile("cp.async.commit_group;" ::: "memory")
#define CP_WAIT(N)  asm volatile("cp.async.wait_group %0;" :: "n"(N) : "memory")

// pack two fp32 into bf16x2 (hi) and residual bf16x2 (lo)
__device__ __forceinline__ void split_pack(float p0, float p1,
                                           uint32_t& hi2, uint32_t& lo2) {
    __nv_bfloat162 h = __floats2bfloat162_rn(p0, p1);
    float r0 = p0 - __bfloat162float(h.x);
    float r1 = p1 - __bfloat162float(h.y);
    __nv_bfloat162 l = __floats2bfloat162_rn(r0, r1);
    hi2 = *(uint32_t*)&h;
    lo2 = *(uint32_t*)&l;
}

// 64B-row swizzle: slot (16B unit) XORed with row bits -> conflict-free ldmatrix
__device__ __forceinline__ uint32_t swz64(int r, int slot) {
    return (uint32_t)(r * 64 + ((slot ^ ((r >> 1) & 3)) << 4));
}
// 128B-row swizzle (SW128)
#define SWZ128(off) ((off) ^ (((off) >> 3) & 0x70))

// ---------------------------------------------------------------------------
// fp32 -> bf16 hi/lo split
// ---------------------------------------------------------------------------
__global__ void __launch_bounds__(256) split_kernel(
    const float* __restrict__ in,
    __nv_bfloat16* __restrict__ hi, __nv_bfloat16* __restrict__ lo, int n4)
{
    int i = blockIdx.x * blockDim.x + threadIdx.x;
    if (i >= n4) return;
    float4 v = ((const float4*)in)[i];
    float f[4] = {v.x, v.y, v.z, v.w};
    unsigned short hs[4], ls[4];
    #pragma unroll
    for (int j = 0; j < 4; j++) {
        __nv_bfloat16 h = __float2bfloat16(f[j]);
        __nv_bfloat16 l = __float2bfloat16(f[j] - __bfloat162float(h));
        hs[j] = *(unsigned short*)&h;
        ls[j] = *(unsigned short*)&l;
    }
    ((ushort4*)hi)[i] = make_ushort4(hs[0], hs[1], hs[2], hs[3]);
    ((ushort4*)lo)[i] = make_ushort4(ls[0], ls[1], ls[2], ls[3]);
}

// ---------------------------------------------------------------------------
// bf16-split mma.sync GEMM: C[M,N] = A[M,K] * B[N,K]^T (fp32-equivalent).
// CTA tile 128x128, K-chunk 32, 8 warps (4m x 2n), warp tile 32x64.
// 3-stage cp.async pipeline, 1 syncthreads/chunk, swizzled 64B rows.
// mode 0: QKV — split into g_{q,k,v}{hi,lo} planes (Q scaled 0.125)
// mode 1: plain fp32 store to Cplain.
// ---------------------------------------------------------------------------
#define KC    32
#define TILEB (128*64)                // 8192 bytes per tile (no padding)
#define BUFB  (4*TILEB)               // 32768 per stage (Ahi,Alo,Bhi,Blo)
#define GEMM_SMEM (3*BUFB)            // 98304

__global__ void __launch_bounds__(256, 2) mma_gemm_kernel(
    const __nv_bfloat16* __restrict__ Ahi, const __nv_bfloat16* __restrict__ Alo,
    const __nv_bfloat16* __restrict__ Bhi, const __nv_bfloat16* __restrict__ Blo,
    float* __restrict__ Cplain, int mode)
{
    extern __shared__ char smc[];
    const uint32_t sb = smem_to_u32(smc);
    const int tid  = threadIdx.x;
    const int wid  = tid >> 5;
    const int lane = tid & 31;
    const int warp_m = (wid & 3) * 32;
    const int warp_n = (wid >> 2) * 64;
    const int row0 = blockIdx.y * 128;
    const int col0 = blockIdx.x * 128;

    float C[2][8][4];
    #pragma unroll
    for (int mi = 0; mi < 2; mi++)
        #pragma unroll
        for (int nf = 0; nf < 8; nf++)
            #pragma unroll
            for (int e = 0; e < 4; e++) C[mi][nf][e] = 0.f;

    // loader coords: 512 slots = 128 rows x 4 x 16B
    const int r_ld[2]   = { tid >> 2, (256 + tid) >> 2 };
    const int slot_ld   = tid & 3;
    const uint32_t so_ld[2] = { swz64(r_ld[0], slot_ld), swz64(r_ld[1], slot_ld) };

    const int NCH = E_ / KC;   // 32

    // issue one K-chunk into stage st
    auto issue = [&](int c, int st) {
        const int k0 = c * KC;
        const uint32_t base = sb + st * BUFB;
        #pragma unroll
        for (int l = 0; l < 2; l++) {
            size_t ga = (size_t)(row0 + r_ld[l]) * E_ + k0 + slot_ld * 8;
            size_t gb = (size_t)(col0 + r_ld[l]) * E_ + k0 + slot_ld * 8;
            cp16(base + 0*TILEB + so_ld[l], Ahi + ga);
            cp16(base + 1*TILEB + so_ld[l], Alo + ga);
            cp16(base + 2*TILEB + so_ld[l], Bhi + gb);
            cp16(base + 3*TILEB + so_ld[l], Blo + gb);
        }
    };

    issue(0, 0); CP_COMMIT();
    issue(1, 1); CP_COMMIT();

    #pragma unroll 1
    for (int c = 0; c < NCH; c++) {
        CP_WAIT(1);              // chunk c complete
        __syncthreads();         // visible to all; stage (c+2)%3 free

        if (c + 2 < NCH) issue(c + 2, (c + 2) % 3);
        CP_COMMIT();             // possibly-empty group keeps the count exact

        const uint32_t stbase = sb + (c % 3) * BUFB;
        const uint32_t bAhi = stbase + 0 * TILEB;
        const uint32_t bAlo = stbase + 1 * TILEB;
        const uint32_t bBhi = stbase + 2 * TILEB;
        const uint32_t bBlo = stbase + 3 * TILEB;

        #pragma unroll
        for (int ki = 0; ki < 2; ki++) {
            const int kf = ki * 16;
            const int aslot = (kf >> 3) + (lane >> 4);
            uint32_t ah[2][4], al[2][4];
            #pragma unroll
            for (int mi = 0; mi < 2; mi++) {
                uint32_t ao = swz64(warp_m + mi * 16 + (lane & 15), aslot);
                ldsm_x4(ah[mi][0], ah[mi][1], ah[mi][2], ah[mi][3], bAhi + ao);
                ldsm_x4(al[mi][0], al[mi][1], al[mi][2], al[mi][3], bAlo + ao);
            }
            const int brow_off = (lane & 7) + ((lane >> 4) & 1) * 8;
            const int bslot    = (kf >> 3) + ((lane >> 3) & 1);
            #pragma unroll
            for (int nj = 0; nj < 4; nj++) {
                uint32_t bo = swz64(warp_n + nj * 16 + brow_off, bslot);
                uint32_t bh0, bh1, bh2, bh3, bl0, bl1, bl2, bl3;
                ldsm_x4(bh0, bh1, bh2, bh3, bBhi + bo);
                ldsm_x4(bl0, bl1, bl2, bl3, bBlo + bo);
                #pragma unroll
                for (int mi = 0; mi < 2; mi++) {
                    float* c0 = C[mi][nj * 2];
                    float* c1 = C[mi][nj * 2 + 1];
                    mma_bf16(c0, ah[mi][0], ah[mi][1], ah[mi][2], ah[mi][3], bh0, bh1);
                    mma_bf16(c0, al[mi][0], al[mi][1], al[mi][2], al[mi][3], bh0, bh1);
                    mma_bf16(c0, ah[mi][0], ah[mi][1], ah[mi][2], ah[mi][3], bl0, bl1);
                    mma_bf16(c1, ah[mi][0], ah[mi][1], ah[mi][2], ah[mi][3], bh2, bh3);
                    mma_bf16(c1, al[mi][0], al[mi][1], al[mi][2], al[mi][3], bh2, bh3);
                    mma_bf16(c1, ah[mi][0], ah[mi][1], ah[mi][2], ah[mi][3], bl2, bl3);
                }
            }
        }
    }

    // ---- epilogue ----
    if (mode == 0) {
        #pragma unroll
        for (int mi = 0; mi < 2; mi++) {
            #pragma unroll
            for (int half = 0; half < 2; half++) {
                int t = row0 + warp_m + mi * 16 + (lane >> 2) + half * 8;
                int bb = t >> 11;
                int ss = t & (S_ - 1);
                #pragma unroll
                for (int nf = 0; nf < 8; nf++) {
                    int f = col0 + warp_n + nf * 8 + (lane & 3) * 2;
                    int which = f >> 10;
                    int rem = f & 1023;
                    int h = rem >> 6;
                    int d = rem & 63;
                    float v0 = C[mi][nf][half * 2];
                    float v1 = C[mi][nf][half * 2 + 1];
                    if (which == 0) { v0 *= 0.125f; v1 *= 0.125f; }
                    uint32_t hi2, lo2;
                    split_pack(v0, v1, hi2, lo2);
                    __nv_bfloat16* dhi = (which == 0) ? g_qhi : ((which == 1) ? g_khi : g_vhi);
                    __nv_bfloat16* dlo = (which == 0) ? g_qlo : ((which == 1) ? g_klo : g_vlo);
                    size_t idx = (((size_t)(bb * H_ + h)) * S_ + ss) * D_ + d;
                    *(uint32_t*)(dhi + idx) = hi2;
                    *(uint32_t*)(dlo + idx) = lo2;
                }
            }
        }
    } else {
        #pragma unroll
        for (int mi = 0; mi < 2; mi++) {
            #pragma unroll
            for (int half = 0; half < 2; half++) {
                int r = row0 + warp_m + mi * 16 + (lane >> 2) + half * 8;
                #pragma unroll
                for (int nf = 0; nf < 8; nf++) {
                    int f = col0 + warp_n + nf * 8 + (lane & 3) * 2;
                    float2 v = make_float2(C[mi][nf][half * 2],
                                           C[mi][nf][half * 2 + 1]);
                    *(float2*)(Cplain + (size_t)r * E_ + f) = v;
                }
            }
        }
    }
}

// ---------------------------------------------------------------------------
// Flash attention (causal) on tensor cores, bf16 hi/lo split.
// CTA: 64 q-rows, 4 warps, kv blocks of 64. SW128 swizzled 128B rows.
// 3-stage cp.async ring for K/V planes, 1 syncthreads per kv block.
// ---------------------------------------------------------------------------
#define APL   8192                    // 64 rows x 128B, one plane
#define KVST  (4*APL)                 // Khi,Klo,Vhi,Vlo per stage = 32768
#define ATTN_SMEM (2*APL + 3*KVST)    // Q planes + 3 stages = 114688 (112KB)

__global__ void __launch_bounds__(128, 2) attn_mma_kernel()
{
    extern __shared__ char sma[];
    const uint32_t sb = smem_to_u32(sma);
    const uint32_t oQhi = 0, oQlo = APL, oKV = 2 * APL;

    const int qb = (int)gridDim.x - 1 - (int)blockIdx.x;  // longest-first
    const int bh = blockIdx.y;
    const int bb = bh >> 4;
    const int hh = bh & 15;
    const int tid  = threadIdx.x;
    const int wid  = tid >> 5;
    const int lane = tid & 31;
    const int warp_m = wid * 16;

    const __nv_bfloat16* Khb = g_khi + (size_t)bh * S_ * D_;
    const __nv_bfloat16* Klb = g_klo + (size_t)bh * S_ * D_;
    const __nv_bfloat16* Vhb = g_vhi + (size_t)bh * S_ * D_;
    const __nv_bfloat16* Vlb = g_vlo + (size_t)bh * S_ * D_;

    // loader coords for one 64x64 bf16 plane: 512 slots = 64 rows x 8 x 16B
    // issue K/V block kb into stage st
    auto issue_kv = [&](int kb, int st) {
        const size_t base = (size_t)(kb * 64) * D_;
        const uint32_t sbase = sb + oKV + st * KVST;
        #pragma unroll
        for (int l = 0; l < 4; l++) {
            int idx = l * 128 + tid;
            int r = idx >> 3, slot = idx & 7;
            uint32_t so = (uint32_t)SWZ128(r * 128 + slot * 16);
            size_t go = base + r * D_ + slot * 8;
            cp16(sbase + 0*APL + so, Khb + go);
            cp16(sbase + 1*APL + so, Klb + go);
            cp16(sbase + 2*APL + so, Vhb + go);
            cp16(sbase + 3*APL + so, Vlb + go);
        }
    };

    issue_kv(0, 0); CP_COMMIT();
    if (qb >= 1) issue_kv(1, 1);
    CP_COMMIT();

    // ---- load Q tile (hi/lo), swizzled ----
    {
        const __nv_bfloat16* Qh = g_qhi + ((size_t)bh * S_ + qb * 64) * D_;
        const __nv_bfloat16* Ql = g_qlo + ((size_t)bh * S_ + qb * 64) * D_;
        #pragma unroll
        for (int l = 0; l < 4; l++) {
            int idx = l * 128 + tid;
            int r = idx >> 3, slot = idx & 7;
            uint32_t so = (uint32_t)SWZ128(r * 128 + slot * 16);
            *(float4*)(sma + oQhi + so) = *(const float4*)(Qh + r * D_ + slot * 8);
            *(float4*)(sma + oQlo + so) = *(const float4*)(Ql + r * D_ + slot * 8);
        }
    }
    __syncthreads();

    // ---- preload Q fragments ----
    uint32_t aqh[4][4], aql[4][4];
    #pragma unroll
    for (int ki = 0; ki < 4; ki++) {
        int row = warp_m + (lane & 15);
        int colb = (ki * 16 + (lane >> 4) * 8) * 2;
        uint32_t ao = (uint32_t)SWZ128(row * 128 + colb);
        ldsm_x4(aqh[ki][0], aqh[ki][1], aqh[ki][2], aqh[ki][3], sb + oQhi + ao);
        ldsm_x4(aql[ki][0], aql[ki][1], aql[ki][2], aql[ki][3], sb + oQlo + ao);
    }

    float m[2]  = {-1e30f, -1e30f};
    float lsum[2] = {0.f, 0.f};
    float o[8][4];
    #pragma unroll
    for (int nf = 0; nf < 8; nf++)
        #pragma unroll
        for (int e = 0; e < 4; e++) o[nf][e] = 0.f;

    #pragma unroll 1
    for (int kb = 0; kb <= qb; kb++) {
        CP_WAIT(1);              // block kb complete
        __syncthreads();         // visible; stage (kb+2)%3 free

        if (kb + 2 <= qb) issue_kv(kb + 2, (kb + 2) % 3);
        CP_COMMIT();

        const uint32_t stb = sb + oKV + (kb % 3) * KVST;
        const uint32_t bKhi = stb, bKlo = stb + APL;
        const uint32_t bVhi = stb + 2*APL, bVlo = stb + 3*APL;

        // ---- scores S = Q . K^T (3-pass hi/lo) ----
        float s[8][4];
        #pragma unroll
        for (int nf = 0; nf < 8; nf++)
            #pragma unroll
            for (int e = 0; e < 4; e++) s[nf][e] = 0.f;

        #pragma unroll
        for (int ki = 0; ki < 4; ki++) {
            const int ro = (lane & 7) + ((lane >> 4) & 1) * 8;
            const int cb = (ki * 16 + ((lane >> 3) & 1) * 8) * 2;
            #pragma unroll
            for (int nj = 0; nj < 4; nj++) {
                uint32_t ad = (uint32_t)SWZ128((nj * 16 + ro) * 128 + cb);
                uint32_t kh0, kh1, kh2, kh3, kl0, kl1, kl2, kl3;
                ldsm_x4(kh0, kh1, kh2, kh3, bKhi + ad);
                ldsm_x4(kl0, kl1, kl2, kl3, bKlo + ad);
                float* c0 = s[nj * 2];
                float* c1 = s[nj * 2 + 1];
                mma_bf16(c0, aqh[ki][0], aqh[ki][1], aqh[ki][2], aqh[ki][3], kh0, kh1);
                mma_bf16(c0, aql[ki][0], aql[ki][1], aql[ki][2], aql[ki][3], kh0, kh1);
                mma_bf16(c0, aqh[ki][0], aqh[ki][1], aqh[ki][2], aqh[ki][3], kl0, kl1);
                mma_bf16(c1, aqh[ki][0], aqh[ki][1], aqh[ki][2], aqh[ki][3], kh2, kh3);
                mma_bf16(c1, aql[ki][0], aql[ki][1], aql[ki][2], aql[ki][3], kh2, kh3);
                mma_bf16(c1, aqh[ki][0], aqh[ki][1], aqh[ki][2], aqh[ki][3], kl2, kl3);
            }
        }

        // ---- causal mask (diagonal block only) ----
        if (kb == qb) {
            const int qrow0 = qb * 64 + warp_m + (lane >> 2);
            #pragma unroll
            for (int nf = 0; nf < 8; nf++) {
                int kcol = kb * 64 + nf * 8 + (lane & 3) * 2;
                #pragma unroll
                for (int e = 0; e < 4; e++) {
                    int q = qrow0 + (e >> 1) * 8;
                    int kv = kcol + (e & 1);
                    if (kv > q) s[nf][e] = -1e30f;
                }
            }
        }

        // ---- online softmax (per row-half) ----
        #pragma unroll
        for (int h = 0; h < 2; h++) {
            float rmax = -1e30f;
            #pragma unroll
            for (int nf = 0; nf < 8; nf++) {
                rmax = fmaxf(rmax, s[nf][2*h]);
                rmax = fmaxf(rmax, s[nf][2*h+1]);
            }
            rmax = fmaxf(rmax, __shfl_xor_sync(0xffffffffu, rmax, 1));
            rmax = fmaxf(rmax, __shfl_xor_sync(0xffffffffu, rmax, 2));

            float mnew = fmaxf(m[h], rmax);
            float corr = __expf(m[h] - mnew);
            m[h] = mnew;

            float rsum = 0.f;
            #pragma unroll
            for (int nf = 0; nf < 8; nf++) {
                float p0 = __expf(s[nf][2*h]   - mnew);
                float p1 = __expf(s[nf][2*h+1] - mnew);
                s[nf][2*h]   = p0;
                s[nf][2*h+1] = p1;
                rsum += p0 + p1;
            }
            rsum += __shfl_xor_sync(0xffffffffu, rsum, 1);
            rsum += __shfl_xor_sync(0xffffffffu, rsum, 2);
            lsum[h] = lsum[h] * corr + rsum;

            #pragma unroll
            for (int nf = 0; nf < 8; nf++) {
                o[nf][2*h]   *= corr;
                o[nf][2*h+1] *= corr;
            }
        }

        // ---- O += P . V (P from regs, V via trans ldmatrix, 3-pass) ----
        #pragma unroll
        for (int ki = 0; ki < 4; ki++) {
            uint32_t aph[4], apl[4];
            split_pack(s[2*ki][0],   s[2*ki][1],   aph[0], apl[0]);
            split_pack(s[2*ki][2],   s[2*ki][3],   aph[1], apl[1]);
            split_pack(s[2*ki+1][0], s[2*ki+1][1], aph[2], apl[2]);
            split_pack(s[2*ki+1][2], s[2*ki+1][3], aph[3], apl[3]);

            const int rowv = ki * 16 + (lane & 7) + ((lane >> 3) & 1) * 8;
            const int cb0  = ((lane >> 4) & 1) * 16;
            #pragma unroll
            for (int nj = 0; nj < 4; nj++) {
                uint32_t ad = (uint32_t)SWZ128(rowv * 128 + cb0 + nj * 32);
                uint32_t vh0, vh1, vh2, vh3, vl0, vl1, vl2, vl3;
                ldsm_x4_trans(vh0, vh1, vh2, vh3, bVhi + ad);
                ldsm_x4_trans(vl0, vl1, vl2, vl3, bVlo + ad);
                float* c0 = o[nj * 2];
                float* c1 = o[nj * 2 + 1];
                mma_bf16(c0, aph[0], aph[1], aph[2], aph[3], vh0, vh1);
                mma_bf16(c0, apl[0], apl[1], apl[2], apl[3], vh0, vh1);
                mma_bf16(c0, aph[0], aph[1], aph[2], aph[3], vl0, vl1);
                mma_bf16(c1, aph[0], aph[1], aph[2], aph[3], vh2, vh3);
                mma_bf16(c1, apl[0], apl[1], apl[2], apl[3], vh2, vh3);
                mma_bf16(c1, aph[0], aph[1], aph[2], aph[3], vl2, vl3);
            }
        }
    }

    // ---- epilogue: O / l, split to bf16 hi/lo planes [B,S,E] ----
    #pragma unroll
    for (int h = 0; h < 2; h++) {
        float inv = 1.0f / lsum[h];
        int r = warp_m + (lane >> 2) + h * 8;
        size_t t = (size_t)(bb * S_ + qb * 64 + r);
        #pragma unroll
        for (int nf = 0; nf < 8; nf++) {
            int dcol = hh * 64 + nf * 8 + (lane & 3) * 2;
            uint32_t hi2, lo2;
            split_pack(o[nf][2*h] * inv, o[nf][2*h+1] * inv, hi2, lo2);
            *(uint32_t*)(g_ohi + t * E_ + dcol) = hi2;
            *(uint32_t*)(g_olo + t * E_ + dcol) = lo2;
        }
    }
}

// ---------------------------------------------------------------------------
extern "C" void kernel_launch(void* const* d_in, const int* in_sizes, int n_in,
                              void* d_out, int out_size)
{
    const float* x     = (const float*)d_in[0];   // [B,S,E]
    const float* w_qkv = (const float*)d_in[1];   // [3E,E]
    const float* w_out = (const float*)d_in[2];   // [E,E]
    float* out = (float*)d_out;                   // [B,S,E]

    __nv_bfloat16 *xhi, *xlo, *wqhi, *wqlo, *wohi, *wolo, *ohi, *olo;
    cudaGetSymbolAddress((void**)&xhi,  g_xhi);
    cudaGetSymbolAddress((void**)&xlo,  g_xlo);
    cudaGetSymbolAddress((void**)&wqhi, g_wqhi);
    cudaGetSymbolAddress((void**)&wqlo, g_wqlo);
    cudaGetSymbolAddress((void**)&wohi, g_wohi);
    cudaGetSymbolAddress((void**)&wolo, g_wolo);
    cudaGetSymbolAddress((void**)&ohi,  g_ohi);
    cudaGetSymbolAddress((void**)&olo,  g_olo);

    static bool attr_set = false;
    if (!attr_set) {
        cudaFuncSetAttribute(mma_gemm_kernel,
                             cudaFuncAttributeMaxDynamicSharedMemorySize,
                             GEMM_SMEM);
        cudaFuncSetAttribute(attn_mma_kernel,
                             cudaFuncAttributeMaxDynamicSharedMemorySize,
                             ATTN_SMEM);
        attr_set = true;
    }

    // 0) fp32 -> bf16 hi/lo splits for X and weights
    {
        int n4 = NT * E_ / 4;
        split_kernel<<<n4 / 256, 256>>>(x, xhi, xlo, n4);
        n4 = F3 * E_ / 4;
        split_kernel<<<n4 / 256, 256>>>(w_qkv, wqhi, wqlo, n4);
        n4 = E_ * E_ / 4;
        split_kernel<<<n4 / 256, 256>>>(w_out, wohi, wolo, n4);
    }

    // 1) QKV projection (tensor cores) -> bf16 hi/lo q/k/v planes
    {
        dim3 grid(F3 / 128, NT / 128);   // (24, 32)
        mma_gemm_kernel<<<grid, 256, GEMM_SMEM>>>(
            xhi, xlo, wqhi, wqlo, nullptr, 0);
    }

    // 2) Flash attention (causal, tensor cores) -> bf16 hi/lo O planes
    {
        dim3 grid(S_ / 64, B_ * H_);     // (32, 32)
        attn_mma_kernel<<<grid, 128, ATTN_SMEM>>>();
    }

    // 3) Output projection (tensor cores) -> fp32 out
    {
        dim3 grid(E_ / 128, NT / 128);   // (8, 32)
        mma_gemm_kernel<<<grid, 256, GEMM_SMEM>>>(
            ohi, olo, wohi, wolo, out, 1);
    }
}